// round 11
// baseline (speedup 1.0000x reference)
#include <cuda_runtime.h>
#include <cuda_bf16.h>
#include <cfloat>
#include <math.h>

// ---------------- problem constants ----------------
#define N_NODES   20000
#define N_EDGES   160000
#define N_IN      300
#define NHID      128
#define HEADS     4
#define NOUT      768
#define NUM_GRAPHS 128

typedef unsigned long long ull;

// ---------------- scratch ----------------
__device__ float g_h0[N_NODES * NHID];
__device__ float g_f1[N_NODES * HEADS * NHID];
__device__ float g_o1[N_NODES * HEADS * NHID];
__device__ float g_f2[N_NODES * NHID];
__device__ float g_o2[N_NODES * NHID];
__device__ float g_aldot[N_NODES * HEADS];
__device__ float g_ardot[N_NODES * HEADS];
__device__ int   g_deg[N_NODES];
__device__ int   g_rowptr[N_NODES + 1];
__device__ int   g_cursor[N_NODES];
__device__ int   g_esrc[N_EDGES];
__device__ float g_pool[NUM_GRAPHS * NHID];

// ---------------- tf32 helpers ----------------
__device__ __forceinline__ unsigned f2tf32(float f) {
    unsigned u;
    asm("cvt.rna.tf32.f32 %0, %1;" : "=r"(u) : "f"(f));
    return u;
}
__device__ __forceinline__ void mma_tf32(float& d0, float& d1, float& d2, float& d3,
                                         unsigned a0, unsigned a1, unsigned a2, unsigned a3,
                                         unsigned b0, unsigned b1) {
    asm("mma.sync.aligned.m16n8k8.row.col.f32.tf32.tf32.f32 "
        "{%0,%1,%2,%3}, {%4,%5,%6,%7}, {%8,%9}, {%0,%1,%2,%3};"
        : "+f"(d0), "+f"(d1), "+f"(d2), "+f"(d3)
        : "r"(a0), "r"(a1), "r"(a2), "r"(a3), "r"(b0), "r"(b1));
}

__device__ __forceinline__ float dot4(float4 a, float4 b) {
    return a.x * b.x + a.y * b.y + a.z * b.z + a.w * b.w;
}

// ---------------- CSR build ----------------
__global__ void zero_int_kernel(int* p, int n) {
    int i = blockIdx.x * blockDim.x + threadIdx.x;
    if (i < n) p[i] = 0;
}

__global__ void hist_kernel(const int* __restrict__ dst, int* __restrict__ deg, int E) {
    int i = blockIdx.x * blockDim.x + threadIdx.x;
    if (i < E) atomicAdd(&deg[dst[i]], 1);
}

__global__ void scan_kernel(const int* __restrict__ deg, int* __restrict__ rowptr,
                            int* __restrict__ cursor) {
    __shared__ int sh[1024];
    const int PER = 20;
    int tid = threadIdx.x;
    int base = tid * PER;
    int loc[PER];
    int s = 0;
    #pragma unroll
    for (int i = 0; i < PER; i++) {
        int idx = base + i;
        int v = (idx < N_NODES) ? deg[idx] : 0;
        loc[i] = s;
        s += v;
    }
    sh[tid] = s;
    __syncthreads();
    #pragma unroll
    for (int off = 1; off < 1024; off <<= 1) {
        int t = (tid >= off) ? sh[tid - off] : 0;
        __syncthreads();
        sh[tid] += t;
        __syncthreads();
    }
    int prev = (tid > 0) ? sh[tid - 1] : 0;
    #pragma unroll
    for (int i = 0; i < PER; i++) {
        int idx = base + i;
        if (idx < N_NODES) {
            int v = prev + loc[i];
            rowptr[idx] = v;
            cursor[idx] = v;
        }
    }
    if (tid == 1023) rowptr[N_NODES] = sh[1023];
}

__global__ void scatter_kernel(const int* __restrict__ src, const int* __restrict__ dst,
                               int* __restrict__ cursor, int* __restrict__ esrc, int E) {
    int i = blockIdx.x * blockDim.x + threadIdx.x;
    if (i < E) {
        int d = dst[i];
        int p = atomicAdd(&cursor[d], 1);
        esrc[p] = src[i];
    }
}

// ---------------- tf32 tensor-core GEMM, double-buffered, templated BM ----------------
// 128 threads (4 warps) for both configs.
// BM=128: warps 2x2, warp tile 64x64 (NI=8) -> minimal smem fragment re-reads.
// BM=64 : warps 1x4, warp tile 64x32 (NI=4).
template<int BM>
__global__ __launch_bounds__(128, 2)
void gemm_tf32_kernel(const float* __restrict__ A, const float* __restrict__ B,
                      const float* __restrict__ bias, float* __restrict__ C,
                      int M, int N, int K, float slope, int act) {
    const int BK = 16;
    const int ASTR = BM + 8;
    const int NI = (BM == 128) ? 8 : 4;     // n-fragments per warp
    const int WN = (BM == 128) ? 64 : 32;   // warp tile N
    const int APF = (BM == 128) ? 4 : 2;    // A prefetch float4s per thread
    __shared__ unsigned As[2][BK * ASTR];
    __shared__ unsigned Bs[2][32 * 33 * 2];

    int tid = threadIdx.x;
    int lane = tid & 31;
    int wid = tid >> 5;
    int warpM = (BM == 128) ? (wid >> 1) : 0;
    int warpN = (BM == 128) ? (wid & 1) : (wid & 3);
    int bm = blockIdx.y * BM, bn = blockIdx.x * 128;
    int g = lane >> 2, c = lane & 3;

    float acc[4][NI][4];
    #pragma unroll
    for (int mi = 0; mi < 4; mi++)
        #pragma unroll
        for (int ni = 0; ni < NI; ni++)
            #pragma unroll
            for (int r = 0; r < 4; r++) acc[mi][ni][r] = 0.f;

    // A loader mapping
    int la_m = (BM == 128) ? tid : (tid >> 1);
    int la_k = (BM == 128) ? 0 : ((tid & 1) * 8);
    int gmA = bm + la_m;
    // B loader mapping (2 passes of 8 rows)
    int lbn = (tid & 15) * 8;
    int b_nb = tid & 15;

    float4 pa[APF];
    float pbv[2][8];

    int nT = (K + BK - 1) / BK;

    auto load_tile = [&](int k0) {
        #pragma unroll
        for (int q = 0; q < APF; q++) {
            int gk = k0 + la_k + q * 4;
            pa[q] = make_float4(0.f, 0.f, 0.f, 0.f);
            if (gmA < M && gk < K)
                pa[q] = *reinterpret_cast<const float4*>(&A[(size_t)gmA * K + gk]);
        }
        #pragma unroll
        for (int pass = 0; pass < 2; pass++) {
            int lbk = (tid >> 4) + pass * 8;
            int gk = k0 + lbk;
            float4 v0 = make_float4(0.f, 0.f, 0.f, 0.f);
            float4 v1 = make_float4(0.f, 0.f, 0.f, 0.f);
            if (gk < K) {
                v0 = *reinterpret_cast<const float4*>(&B[(size_t)gk * N + bn + lbn]);
                v1 = *reinterpret_cast<const float4*>(&B[(size_t)gk * N + bn + lbn + 4]);
            }
            pbv[pass][0] = v0.x; pbv[pass][1] = v0.y; pbv[pass][2] = v0.z; pbv[pass][3] = v0.w;
            pbv[pass][4] = v1.x; pbv[pass][5] = v1.y; pbv[pass][6] = v1.z; pbv[pass][7] = v1.w;
        }
    };
    auto store_tile = [&](int buf) {
        #pragma unroll
        for (int q = 0; q < APF; q++) {
            int kk = la_k + q * 4;
            As[buf][(kk + 0) * ASTR + la_m] = f2tf32(pa[q].x);
            As[buf][(kk + 1) * ASTR + la_m] = f2tf32(pa[q].y);
            As[buf][(kk + 2) * ASTR + la_m] = f2tf32(pa[q].z);
            As[buf][(kk + 3) * ASTR + la_m] = f2tf32(pa[q].w);
        }
        #pragma unroll
        for (int pass = 0; pass < 2; pass++) {
            int lbk = (tid >> 4) + pass * 8;
            int b_kb = lbk >> 3;
            int b_c = lbk & 3;
            int b_half = (lbk & 7) >> 2;
            int grp = b_kb * 16 + b_nb;
            #pragma unroll
            for (int j = 0; j < 8; j++) {
                int u = grp * 33 + j * 4 + b_c;
                Bs[buf][2 * u + b_half] = f2tf32(pbv[pass][j]);
            }
        }
    };

    load_tile(0);
    store_tile(0);
    __syncthreads();

    for (int t = 0; t < nT; t++) {
        int buf = t & 1;
        bool more = (t + 1) < nT;
        if (more) load_tile((t + 1) * BK);

        #pragma unroll
        for (int kb = 0; kb < 2; kb++) {
            unsigned af[4][4];
            int r0 = (kb * 8 + c) * ASTR;
            int r1 = (kb * 8 + c + 4) * ASTR;
            #pragma unroll
            for (int mi = 0; mi < 4; mi++) {
                int m0 = warpM * 64 + mi * 16;
                af[mi][0] = As[buf][r0 + m0 + g];
                af[mi][1] = As[buf][r0 + m0 + g + 8];
                af[mi][2] = As[buf][r1 + m0 + g];
                af[mi][3] = As[buf][r1 + m0 + g + 8];
            }
            unsigned bf[NI][2];
            #pragma unroll
            for (int ni = 0; ni < NI; ni++) {
                int grp = kb * 16 + warpN * (WN / 8) + ni;
                uint2 tt = *reinterpret_cast<const uint2*>(&Bs[buf][2 * (grp * 33 + lane)]);
                bf[ni][0] = tt.x;
                bf[ni][1] = tt.y;
            }
            #pragma unroll
            for (int mi = 0; mi < 4; mi++)
                #pragma unroll
                for (int ni = 0; ni < NI; ni++)
                    mma_tf32(acc[mi][ni][0], acc[mi][ni][1], acc[mi][ni][2], acc[mi][ni][3],
                             af[mi][0], af[mi][1], af[mi][2], af[mi][3],
                             bf[ni][0], bf[ni][1]);
        }

        if (more) store_tile(1 - buf);
        __syncthreads();
    }

    // ---- epilogue ----
    #pragma unroll
    for (int mi = 0; mi < 4; mi++) {
        int row0 = bm + warpM * 64 + mi * 16 + g;
        #pragma unroll
        for (int ni = 0; ni < NI; ni++) {
            int col = bn + warpN * WN + ni * 8 + c * 2;
            float bv0 = bias ? bias[col] : 0.f;
            float bv1 = bias ? bias[col + 1] : 0.f;
            if (row0 < M) {
                float x0 = acc[mi][ni][0] + bv0;
                float x1 = acc[mi][ni][1] + bv1;
                if (act) {
                    x0 = x0 > 0.f ? x0 : slope * x0;
                    x1 = x1 > 0.f ? x1 : slope * x1;
                }
                *reinterpret_cast<float2*>(&C[(size_t)row0 * N + col]) = make_float2(x0, x1);
            }
            int row1 = row0 + 8;
            if (row1 < M) {
                float x2 = acc[mi][ni][2] + bv0;
                float x3 = acc[mi][ni][3] + bv1;
                if (act) {
                    x2 = x2 > 0.f ? x2 : slope * x2;
                    x3 = x3 > 0.f ? x3 : slope * x3;
                }
                *reinterpret_cast<float2*>(&C[(size_t)row1 * N + col]) = make_float2(x2, x3);
            }
        }
    }
}

// ---------------- precompute attention dots ----------------
template<int H>
__global__ void attdot_kernel(const float* __restrict__ feat,
                              const float* __restrict__ attL, const float* __restrict__ attR,
                              float* __restrict__ aldot, float* __restrict__ ardot) {
    int warp = (blockIdx.x * blockDim.x + threadIdx.x) >> 5;
    int lane = threadIdx.x & 31;
    if (warp >= N_NODES * H) return;
    int nid = warp / H, h = warp % H;
    float4 x = reinterpret_cast<const float4*>(feat + ((size_t)nid * H + h) * NHID)[lane];
    float4 aL = reinterpret_cast<const float4*>(attL + h * NHID)[lane];
    float4 aR = reinterpret_cast<const float4*>(attR + h * NHID)[lane];
    float al = dot4(x, aL);
    float ar = dot4(x, aR);
    #pragma unroll
    for (int o = 16; o; o >>= 1) {
        al += __shfl_xor_sync(0xffffffffu, al, o);
        ar += __shfl_xor_sync(0xffffffffu, ar, o);
    }
    if (lane == 0) { aldot[warp] = al; ardot[warp] = ar; }
}

// ---------------- SuperGAT aggregation: one warp per (node, head), 4-edge unroll ----------------
template<int H>
__global__ void agg_kernel(const float* __restrict__ feat,
                           const float* __restrict__ aldot, const float* __restrict__ ardot,
                           const float* __restrict__ bias,
                           const int* __restrict__ rowptr, const int* __restrict__ esrc,
                           float* __restrict__ out, float out_slope) {
    const int C = NHID;
    int warp = (blockIdx.x * blockDim.x + threadIdx.x) >> 5;
    int lane = threadIdx.x & 31;
    if (warp >= N_NODES * H) return;
    int nid = warp / H;
    int h   = warp % H;

    float4 xi = reinterpret_cast<const float4*>(feat + ((size_t)nid * H + h) * C)[lane];
    float ar = ardot[warp];

    float m = -INFINITY, s = 0.f;
    float4 acc = make_float4(0.f, 0.f, 0.f, 0.f);

    int e0 = rowptr[nid], e1 = rowptr[nid + 1];
    int e = e0;
    for (; e + 3 < e1; e += 4) {
        int s0 = esrc[e], s1 = esrc[e + 1], s2 = esrc[e + 2], s3 = esrc[e + 3];
        float4 xj0 = reinterpret_cast<const float4*>(feat + ((size_t)s0 * H + h) * C)[lane];
        float4 xj1 = reinterpret_cast<const float4*>(feat + ((size_t)s1 * H + h) * C)[lane];
        float4 xj2 = reinterpret_cast<const float4*>(feat + ((size_t)s2 * H + h) * C)[lane];
        float4 xj3 = reinterpret_cast<const float4*>(feat + ((size_t)s3 * H + h) * C)[lane];
        float lg0 = dot4(xi, xj0), lg1 = dot4(xi, xj1);
        float lg2 = dot4(xi, xj2), lg3 = dot4(xi, xj3);
        #pragma unroll
        for (int o = 16; o; o >>= 1) {
            lg0 += __shfl_xor_sync(0xffffffffu, lg0, o);
            lg1 += __shfl_xor_sync(0xffffffffu, lg1, o);
            lg2 += __shfl_xor_sync(0xffffffffu, lg2, o);
            lg3 += __shfl_xor_sync(0xffffffffu, lg3, o);
        }
        float a0 = (aldot[s0 * H + h] + ar) * (1.f / (1.f + __expf(-lg0)));
        float a1 = (aldot[s1 * H + h] + ar) * (1.f / (1.f + __expf(-lg1)));
        float a2 = (aldot[s2 * H + h] + ar) * (1.f / (1.f + __expf(-lg2)));
        float a3 = (aldot[s3 * H + h] + ar) * (1.f / (1.f + __expf(-lg3)));
        a0 = a0 > 0.f ? a0 : 0.2f * a0;
        a1 = a1 > 0.f ? a1 : 0.2f * a1;
        a2 = a2 > 0.f ? a2 : 0.2f * a2;
        a3 = a3 > 0.f ? a3 : 0.2f * a3;
        float mx = fmaxf(fmaxf(a0, a1), fmaxf(a2, a3));
        float mn = fmaxf(m, mx);
        float sc = __expf(m - mn);
        float w0 = __expf(a0 - mn), w1 = __expf(a1 - mn);
        float w2 = __expf(a2 - mn), w3 = __expf(a3 - mn);
        s = s * sc + w0 + w1 + w2 + w3;
        acc.x = acc.x * sc + w0 * xj0.x + w1 * xj1.x + w2 * xj2.x + w3 * xj3.x;
        acc.y = acc.y * sc + w0 * xj0.y + w1 * xj1.y + w2 * xj2.y + w3 * xj3.y;
        acc.z = acc.z * sc + w0 * xj0.z + w1 * xj1.z + w2 * xj2.z + w3 * xj3.z;
        acc.w = acc.w * sc + w0 * xj0.w + w1 * xj1.w + w2 * xj2.w + w3 * xj3.w;
        m = mn;
    }
    for (; e < e1; e++) {
        int sn = esrc[e];
        float4 xj = reinterpret_cast<const float4*>(feat + ((size_t)sn * H + h) * C)[lane];
        float lg = dot4(xi, xj);
        #pragma unroll
        for (int o = 16; o; o >>= 1) lg += __shfl_xor_sync(0xffffffffu, lg, o);
        float al = aldot[sn * H + h];
        float a = (al + ar) * (1.f / (1.f + __expf(-lg)));
        a = a > 0.f ? a : 0.2f * a;
        float mn = fmaxf(m, a);
        float sc = __expf(m - mn);
        float w = __expf(a - mn);
        s = s * sc + w;
        acc.x = acc.x * sc + w * xj.x;
        acc.y = acc.y * sc + w * xj.y;
        acc.z = acc.z * sc + w * xj.z;
        acc.w = acc.w * sc + w * xj.w;
        m = mn;
    }
    float inv = 1.f / (s + 1e-16f);
    float4 b4 = reinterpret_cast<const float4*>(bias + h * C)[lane];
    float4 r;
    r.x = acc.x * inv + b4.x; r.x = r.x > 0.f ? r.x : out_slope * r.x;
    r.y = acc.y * inv + b4.y; r.y = r.y > 0.f ? r.y : out_slope * r.y;
    r.z = acc.z * inv + b4.z; r.z = r.z > 0.f ? r.z : out_slope * r.z;
    r.w = acc.w * inv + b4.w; r.w = r.w > 0.f ? r.w : out_slope * r.w;
    reinterpret_cast<float4*>(out + ((size_t)nid * H + h) * C)[lane] = r;
}

// ---------------- graph pooling ----------------
__global__ void pool_init_kernel(float* pool) {
    int i = blockIdx.x * blockDim.x + threadIdx.x;
    if (i < NUM_GRAPHS * NHID) pool[i] = -FLT_MAX;
}

__device__ __forceinline__ void atomicMaxF(float* a, float v) {
    if (v >= 0.f) atomicMax((int*)a, __float_as_int(v));
    else          atomicMin((unsigned int*)a, __float_as_uint(v));
}

__global__ void pool_max_kernel(const float* __restrict__ x, const int* __restrict__ batch,
                                float* __restrict__ pool) {
    int i = blockIdx.x * blockDim.x + threadIdx.x;
    if (i >= N_NODES * NHID) return;
    int n = i / NHID, c = i % NHID;
    atomicMaxF(&pool[batch[n] * NHID + c], x[i]);
}

// ---------------- launch ----------------
static inline float* symf(const void* sym) {
    void* p = nullptr; cudaGetSymbolAddress(&p, sym); return (float*)p;
}
static inline int* symi(const void* sym) {
    void* p = nullptr; cudaGetSymbolAddress(&p, sym); return (int*)p;
}

extern "C" void kernel_launch(void* const* d_in, const int* in_sizes, int n_in,
                              void* d_out, int out_size) {
    const float* x      = (const float*)d_in[0];
    const int*   eidx   = (const int*)  d_in[1];
    const int*   batch  = (const int*)  d_in[2];
    const float* fc1_w  = (const float*)d_in[3];
    const float* fc1_b  = (const float*)d_in[4];
    const float* w1     = (const float*)d_in[5];
    const float* att_l1 = (const float*)d_in[6];
    const float* att_r1 = (const float*)d_in[7];
    const float* b1     = (const float*)d_in[8];
    const float* w2     = (const float*)d_in[9];
    const float* att_l2 = (const float*)d_in[10];
    const float* att_r2 = (const float*)d_in[11];
    const float* b2     = (const float*)d_in[12];
    const float* fc2_w  = (const float*)d_in[13];
    const float* fc2_b  = (const float*)d_in[14];
    float* out = (float*)d_out;

    const int* e_src = eidx;
    const int* e_dst = eidx + N_EDGES;

    float* h0 = symf(g_h0); float* f1 = symf(g_f1); float* o1 = symf(g_o1);
    float* f2 = symf(g_f2); float* o2 = symf(g_o2); float* pool = symf(g_pool);
    float* aldot = symf(g_aldot); float* ardot = symf(g_ardot);
    int* deg = symi(g_deg); int* rowptr = symi(g_rowptr);
    int* cursor = symi(g_cursor); int* esrc = symi(g_esrc);

    zero_int_kernel<<<(N_NODES + 255) / 256, 256>>>(deg, N_NODES);                     // 0
    hist_kernel<<<(N_EDGES + 255) / 256, 256>>>(e_dst, deg, N_EDGES);                  // 1

    // GEMM1: h0 = leaky(x @ fc1_w + fc1_b)  [20000,300]x[300,128] BM=64
    {
        dim3 grid(NHID / 128, (N_NODES + 63) / 64);
        gemm_tf32_kernel<64><<<grid, 128>>>(x, fc1_w, fc1_b, h0, N_NODES, NHID, N_IN, 0.01f, 1); // 2
    }
    // GEMM2: f1 = h0 @ w1   [20000,128]x[128,512]  (profiled slot 3, BM=128, new 2x2 warp layout)
    {
        dim3 grid(HEADS * NHID / 128, (N_NODES + 127) / 128);
        gemm_tf32_kernel<128><<<grid, 128>>>(h0, w1, nullptr, f1, N_NODES, HEADS * NHID, NHID, 0.f, 0); // 3
    }

    scan_kernel<<<1, 1024>>>(deg, rowptr, cursor);                                     // 4
    scatter_kernel<<<(N_EDGES + 255) / 256, 256>>>(e_src, e_dst, cursor, esrc, N_EDGES); // 5

    {
        int warps = N_NODES * HEADS;
        attdot_kernel<HEADS><<<(warps * 32 + 255) / 256, 256>>>(f1, att_l1, att_r1, aldot, ardot); // 6
    }
    // Aggregation layer 1
    {
        int warps = N_NODES * HEADS;
        agg_kernel<HEADS><<<(warps * 32 + 255) / 256, 256>>>(f1, aldot, ardot, b1,
                                                             rowptr, esrc, o1, 0.01f); // 7
    }
    // GEMM3: f2 = o1 @ w2   [20000,512]x[512,128] BM=64
    {
        dim3 grid(NHID / 128, (N_NODES + 63) / 64);
        gemm_tf32_kernel<64><<<grid, 128>>>(o1, w2, nullptr, f2, N_NODES, NHID, HEADS * NHID, 0.f, 0); // 8
    }
    {
        int warps = N_NODES;
        attdot_kernel<1><<<(warps * 32 + 255) / 256, 256>>>(f2, att_l2, att_r2, aldot, ardot); // 9
    }
    // Aggregation layer 2
    {
        int warps = N_NODES;
        agg_kernel<1><<<(warps * 32 + 255) / 256, 256>>>(f2, aldot, ardot, b2,
                                                         rowptr, esrc, o2, 0.01f);     // 10
    }
    pool_init_kernel<<<(NUM_GRAPHS * NHID + 255) / 256, 256>>>(pool);                  // 11
    pool_max_kernel<<<(N_NODES * NHID + 255) / 256, 256>>>(o2, batch, pool);           // 12

    // GEMM4: out = pool @ fc2_w + fc2_b   [128,128]x[128,768]  BM=128
    {
        dim3 grid(NOUT / 128, (NUM_GRAPHS + 127) / 128);
        gemm_tf32_kernel<128><<<grid, 128>>>(pool, fc2_w, fc2_b, out, NUM_GRAPHS, NOUT, NHID, 0.f, 0); // 13
    }
}

// round 12
// speedup vs baseline: 1.0527x; 1.0527x over previous
#include <cuda_runtime.h>
#include <cuda_bf16.h>
#include <cfloat>
#include <math.h>

// ---------------- problem constants ----------------
#define N_NODES   20000
#define N_EDGES   160000
#define N_IN      300
#define NHID      128
#define HEADS     4
#define NOUT      768
#define NUM_GRAPHS 128

typedef unsigned long long ull;

// ---------------- scratch ----------------
__device__ float g_h0[N_NODES * NHID];
__device__ float g_f1[N_NODES * HEADS * NHID];
__device__ float g_o1[N_NODES * HEADS * NHID];
__device__ float g_f2[N_NODES * NHID];
__device__ float g_o2[N_NODES * NHID];
__device__ float g_aldot[N_NODES * HEADS];
__device__ float g_ardot[N_NODES * HEADS];
__device__ int   g_deg[N_NODES];
__device__ int   g_rowptr[N_NODES + 1];
__device__ int   g_cursor[N_NODES];
__device__ int   g_esrc[N_EDGES];
__device__ float g_pool[NUM_GRAPHS * NHID];

// ---------------- tf32 helpers ----------------
__device__ __forceinline__ unsigned f2tf32(float f) {
    unsigned u;
    asm("cvt.rna.tf32.f32 %0, %1;" : "=r"(u) : "f"(f));
    return u;
}
__device__ __forceinline__ void mma_tf32(float& d0, float& d1, float& d2, float& d3,
                                         unsigned a0, unsigned a1, unsigned a2, unsigned a3,
                                         unsigned b0, unsigned b1) {
    asm("mma.sync.aligned.m16n8k8.row.col.f32.tf32.tf32.f32 "
        "{%0,%1,%2,%3}, {%4,%5,%6,%7}, {%8,%9}, {%0,%1,%2,%3};"
        : "+f"(d0), "+f"(d1), "+f"(d2), "+f"(d3)
        : "r"(a0), "r"(a1), "r"(a2), "r"(a3), "r"(b0), "r"(b1));
}

__device__ __forceinline__ float dot4(float4 a, float4 b) {
    return a.x * b.x + a.y * b.y + a.z * b.z + a.w * b.w;
}

// ---------------- CSR build ----------------
__global__ void zero_int_kernel(int* p, int n) {
    int i = blockIdx.x * blockDim.x + threadIdx.x;
    if (i < n) p[i] = 0;
}

__global__ void hist_kernel(const int* __restrict__ dst, int* __restrict__ deg, int E) {
    int i = blockIdx.x * blockDim.x + threadIdx.x;
    if (i < E) atomicAdd(&deg[dst[i]], 1);
}

__global__ void scan_kernel(const int* __restrict__ deg, int* __restrict__ rowptr,
                            int* __restrict__ cursor) {
    __shared__ int sh[1024];
    const int PER = 20;
    int tid = threadIdx.x;
    int base = tid * PER;
    int loc[PER];
    int s = 0;
    #pragma unroll
    for (int i = 0; i < PER; i++) {
        int idx = base + i;
        int v = (idx < N_NODES) ? deg[idx] : 0;
        loc[i] = s;
        s += v;
    }
    sh[tid] = s;
    __syncthreads();
    #pragma unroll
    for (int off = 1; off < 1024; off <<= 1) {
        int t = (tid >= off) ? sh[tid - off] : 0;
        __syncthreads();
        sh[tid] += t;
        __syncthreads();
    }
    int prev = (tid > 0) ? sh[tid - 1] : 0;
    #pragma unroll
    for (int i = 0; i < PER; i++) {
        int idx = base + i;
        if (idx < N_NODES) {
            int v = prev + loc[i];
            rowptr[idx] = v;
            cursor[idx] = v;
        }
    }
    if (tid == 1023) rowptr[N_NODES] = sh[1023];
}

__global__ void scatter_kernel(const int* __restrict__ src, const int* __restrict__ dst,
                               int* __restrict__ cursor, int* __restrict__ esrc, int E) {
    int i = blockIdx.x * blockDim.x + threadIdx.x;
    if (i < E) {
        int d = dst[i];
        int p = atomicAdd(&cursor[d], 1);
        esrc[p] = src[i];
    }
}

// ---------------- tf32 tensor-core GEMM, double-buffered (R10-proven) ----------------
// THREADS = 2*BM. Warp tile 64x32; BM=128: 8 warps (2x4); BM=64: 4 warps (1x4).
template<int BM>
__global__ __launch_bounds__(2 * BM)
void gemm_tf32_kernel(const float* __restrict__ A, const float* __restrict__ B,
                      const float* __restrict__ bias, float* __restrict__ C,
                      int M, int N, int K, float slope, int act) {
    const int BK = 16;
    const int ASTR = BM + 8;
    const int THREADS = 2 * BM;
    const int BROWS = THREADS / 16;
    const int BPASS = 16 / BROWS;
    __shared__ unsigned As[2][BK * ASTR];
    __shared__ unsigned Bs[2][32 * 33 * 2];

    int tid = threadIdx.x;
    int lane = tid & 31;
    int wid = tid >> 5;
    int warpM = wid >> 2;
    int warpN = wid & 3;
    int bm = blockIdx.y * BM, bn = blockIdx.x * 128;
    int g = lane >> 2, c = lane & 3;

    float acc[4][4][4];
    #pragma unroll
    for (int mi = 0; mi < 4; mi++)
        #pragma unroll
        for (int ni = 0; ni < 4; ni++)
            #pragma unroll
            for (int r = 0; r < 4; r++) acc[mi][ni][r] = 0.f;

    int la_m = tid >> 1;
    int la_k = (tid & 1) * 8;
    int gmA = bm + la_m;
    int lbn = (tid & 15) * 8;
    int b_nb = tid & 15;

    float4 pa0, pa1;
    float pbv[BPASS][8];

    int nT = (K + BK - 1) / BK;

    auto load_tile = [&](int k0) {
        pa0 = make_float4(0.f, 0.f, 0.f, 0.f);
        pa1 = make_float4(0.f, 0.f, 0.f, 0.f);
        int gk0 = k0 + la_k;
        if (gmA < M && gk0 < K)
            pa0 = *reinterpret_cast<const float4*>(&A[(size_t)gmA * K + gk0]);
        if (gmA < M && gk0 + 4 < K)
            pa1 = *reinterpret_cast<const float4*>(&A[(size_t)gmA * K + gk0 + 4]);
        #pragma unroll
        for (int pass = 0; pass < BPASS; pass++) {
            int lbk = (tid >> 4) + pass * BROWS;
            int gk = k0 + lbk;
            float4 v0 = make_float4(0.f, 0.f, 0.f, 0.f);
            float4 v1 = make_float4(0.f, 0.f, 0.f, 0.f);
            if (gk < K) {
                v0 = *reinterpret_cast<const float4*>(&B[(size_t)gk * N + bn + lbn]);
                v1 = *reinterpret_cast<const float4*>(&B[(size_t)gk * N + bn + lbn + 4]);
            }
            pbv[pass][0] = v0.x; pbv[pass][1] = v0.y; pbv[pass][2] = v0.z; pbv[pass][3] = v0.w;
            pbv[pass][4] = v1.x; pbv[pass][5] = v1.y; pbv[pass][6] = v1.z; pbv[pass][7] = v1.w;
        }
    };
    auto store_tile = [&](int buf) {
        As[buf][(la_k + 0) * ASTR + la_m] = f2tf32(pa0.x);
        As[buf][(la_k + 1) * ASTR + la_m] = f2tf32(pa0.y);
        As[buf][(la_k + 2) * ASTR + la_m] = f2tf32(pa0.z);
        As[buf][(la_k + 3) * ASTR + la_m] = f2tf32(pa0.w);
        As[buf][(la_k + 4) * ASTR + la_m] = f2tf32(pa1.x);
        As[buf][(la_k + 5) * ASTR + la_m] = f2tf32(pa1.y);
        As[buf][(la_k + 6) * ASTR + la_m] = f2tf32(pa1.z);
        As[buf][(la_k + 7) * ASTR + la_m] = f2tf32(pa1.w);
        #pragma unroll
        for (int pass = 0; pass < BPASS; pass++) {
            int lbk = (tid >> 4) + pass * BROWS;
            int b_kb = lbk >> 3;
            int b_c = lbk & 3;
            int b_half = (lbk & 7) >> 2;
            int grp = b_kb * 16 + b_nb;
            #pragma unroll
            for (int j = 0; j < 8; j++) {
                int u = grp * 33 + j * 4 + b_c;
                Bs[buf][2 * u + b_half] = f2tf32(pbv[pass][j]);
            }
        }
    };

    load_tile(0);
    store_tile(0);
    __syncthreads();

    for (int t = 0; t < nT; t++) {
        int buf = t & 1;
        bool more = (t + 1) < nT;
        if (more) load_tile((t + 1) * BK);

        #pragma unroll
        for (int kb = 0; kb < 2; kb++) {
            unsigned af[4][4];
            int r0 = (kb * 8 + c) * ASTR;
            int r1 = (kb * 8 + c + 4) * ASTR;
            #pragma unroll
            for (int mi = 0; mi < 4; mi++) {
                int m0 = warpM * 64 + mi * 16;
                af[mi][0] = As[buf][r0 + m0 + g];
                af[mi][1] = As[buf][r0 + m0 + g + 8];
                af[mi][2] = As[buf][r1 + m0 + g];
                af[mi][3] = As[buf][r1 + m0 + g + 8];
            }
            unsigned bf[4][2];
            #pragma unroll
            for (int ni = 0; ni < 4; ni++) {
                int grp = kb * 16 + warpN * 4 + ni;
                uint2 tt = *reinterpret_cast<const uint2*>(&Bs[buf][2 * (grp * 33 + lane)]);
                bf[ni][0] = tt.x;
                bf[ni][1] = tt.y;
            }
            #pragma unroll
            for (int mi = 0; mi < 4; mi++)
                #pragma unroll
                for (int ni = 0; ni < 4; ni++)
                    mma_tf32(acc[mi][ni][0], acc[mi][ni][1], acc[mi][ni][2], acc[mi][ni][3],
                             af[mi][0], af[mi][1], af[mi][2], af[mi][3],
                             bf[ni][0], bf[ni][1]);
        }

        if (more) store_tile(1 - buf);
        __syncthreads();
    }

    #pragma unroll
    for (int mi = 0; mi < 4; mi++) {
        int row0 = bm + warpM * 64 + mi * 16 + g;
        #pragma unroll
        for (int ni = 0; ni < 4; ni++) {
            int col = bn + warpN * 32 + ni * 8 + c * 2;
            float bv0 = bias ? bias[col] : 0.f;
            float bv1 = bias ? bias[col + 1] : 0.f;
            if (row0 < M) {
                float x0 = acc[mi][ni][0] + bv0;
                float x1 = acc[mi][ni][1] + bv1;
                if (act) {
                    x0 = x0 > 0.f ? x0 : slope * x0;
                    x1 = x1 > 0.f ? x1 : slope * x1;
                }
                *reinterpret_cast<float2*>(&C[(size_t)row0 * N + col]) = make_float2(x0, x1);
            }
            int row1 = row0 + 8;
            if (row1 < M) {
                float x2 = acc[mi][ni][2] + bv0;
                float x3 = acc[mi][ni][3] + bv1;
                if (act) {
                    x2 = x2 > 0.f ? x2 : slope * x2;
                    x3 = x3 > 0.f ? x3 : slope * x3;
                }
                *reinterpret_cast<float2*>(&C[(size_t)row1 * N + col]) = make_float2(x2, x3);
            }
        }
    }
}

// ---------------- precompute attention dots ----------------
template<int H>
__global__ void attdot_kernel(const float* __restrict__ feat,
                              const float* __restrict__ attL, const float* __restrict__ attR,
                              float* __restrict__ aldot, float* __restrict__ ardot) {
    int warp = (blockIdx.x * blockDim.x + threadIdx.x) >> 5;
    int lane = threadIdx.x & 31;
    if (warp >= N_NODES * H) return;
    int nid = warp / H, h = warp % H;
    float4 x = reinterpret_cast<const float4*>(feat + ((size_t)nid * H + h) * NHID)[lane];
    float4 aL = reinterpret_cast<const float4*>(attL + h * NHID)[lane];
    float4 aR = reinterpret_cast<const float4*>(attR + h * NHID)[lane];
    float al = dot4(x, aL);
    float ar = dot4(x, aR);
    #pragma unroll
    for (int o = 16; o; o >>= 1) {
        al += __shfl_xor_sync(0xffffffffu, al, o);
        ar += __shfl_xor_sync(0xffffffffu, ar, o);
    }
    if (lane == 0) { aldot[warp] = al; ardot[warp] = ar; }
}

// ---------------- SuperGAT aggregation: one warp per (node, head), 4-edge unroll ----------------
template<int H>
__global__ void agg_kernel(const float* __restrict__ feat,
                           const float* __restrict__ aldot, const float* __restrict__ ardot,
                           const float* __restrict__ bias,
                           const int* __restrict__ rowptr, const int* __restrict__ esrc,
                           float* __restrict__ out, float out_slope) {
    const int C = NHID;
    int warp = (blockIdx.x * blockDim.x + threadIdx.x) >> 5;
    int lane = threadIdx.x & 31;
    if (warp >= N_NODES * H) return;
    int nid = warp / H;
    int h   = warp % H;

    float4 xi = reinterpret_cast<const float4*>(feat + ((size_t)nid * H + h) * C)[lane];
    float ar = ardot[warp];

    float m = -INFINITY, s = 0.f;
    float4 acc = make_float4(0.f, 0.f, 0.f, 0.f);

    int e0 = rowptr[nid], e1 = rowptr[nid + 1];
    int e = e0;
    for (; e + 3 < e1; e += 4) {
        int s0 = esrc[e], s1 = esrc[e + 1], s2 = esrc[e + 2], s3 = esrc[e + 3];
        float4 xj0 = reinterpret_cast<const float4*>(feat + ((size_t)s0 * H + h) * C)[lane];
        float4 xj1 = reinterpret_cast<const float4*>(feat + ((size_t)s1 * H + h) * C)[lane];
        float4 xj2 = reinterpret_cast<const float4*>(feat + ((size_t)s2 * H + h) * C)[lane];
        float4 xj3 = reinterpret_cast<const float4*>(feat + ((size_t)s3 * H + h) * C)[lane];
        float lg0 = dot4(xi, xj0), lg1 = dot4(xi, xj1);
        float lg2 = dot4(xi, xj2), lg3 = dot4(xi, xj3);
        #pragma unroll
        for (int o = 16; o; o >>= 1) {
            lg0 += __shfl_xor_sync(0xffffffffu, lg0, o);
            lg1 += __shfl_xor_sync(0xffffffffu, lg1, o);
            lg2 += __shfl_xor_sync(0xffffffffu, lg2, o);
            lg3 += __shfl_xor_sync(0xffffffffu, lg3, o);
        }
        float a0 = (aldot[s0 * H + h] + ar) * (1.f / (1.f + __expf(-lg0)));
        float a1 = (aldot[s1 * H + h] + ar) * (1.f / (1.f + __expf(-lg1)));
        float a2 = (aldot[s2 * H + h] + ar) * (1.f / (1.f + __expf(-lg2)));
        float a3 = (aldot[s3 * H + h] + ar) * (1.f / (1.f + __expf(-lg3)));
        a0 = a0 > 0.f ? a0 : 0.2f * a0;
        a1 = a1 > 0.f ? a1 : 0.2f * a1;
        a2 = a2 > 0.f ? a2 : 0.2f * a2;
        a3 = a3 > 0.f ? a3 : 0.2f * a3;
        float mx = fmaxf(fmaxf(a0, a1), fmaxf(a2, a3));
        float mn = fmaxf(m, mx);
        float sc = __expf(m - mn);
        float w0 = __expf(a0 - mn), w1 = __expf(a1 - mn);
        float w2 = __expf(a2 - mn), w3 = __expf(a3 - mn);
        s = s * sc + w0 + w1 + w2 + w3;
        acc.x = acc.x * sc + w0 * xj0.x + w1 * xj1.x + w2 * xj2.x + w3 * xj3.x;
        acc.y = acc.y * sc + w0 * xj0.y + w1 * xj1.y + w2 * xj2.y + w3 * xj3.y;
        acc.z = acc.z * sc + w0 * xj0.z + w1 * xj1.z + w2 * xj2.z + w3 * xj3.z;
        acc.w = acc.w * sc + w0 * xj0.w + w1 * xj1.w + w2 * xj2.w + w3 * xj3.w;
        m = mn;
    }
    for (; e < e1; e++) {
        int sn = esrc[e];
        float4 xj = reinterpret_cast<const float4*>(feat + ((size_t)sn * H + h) * C)[lane];
        float lg = dot4(xi, xj);
        #pragma unroll
        for (int o = 16; o; o >>= 1) lg += __shfl_xor_sync(0xffffffffu, lg, o);
        float al = aldot[sn * H + h];
        float a = (al + ar) * (1.f / (1.f + __expf(-lg)));
        a = a > 0.f ? a : 0.2f * a;
        float mn = fmaxf(m, a);
        float sc = __expf(m - mn);
        float w = __expf(a - mn);
        s = s * sc + w;
        acc.x = acc.x * sc + w * xj.x;
        acc.y = acc.y * sc + w * xj.y;
        acc.z = acc.z * sc + w * xj.z;
        acc.w = acc.w * sc + w * xj.w;
        m = mn;
    }
    float inv = 1.f / (s + 1e-16f);
    float4 b4 = reinterpret_cast<const float4*>(bias + h * C)[lane];
    float4 r;
    r.x = acc.x * inv + b4.x; r.x = r.x > 0.f ? r.x : out_slope * r.x;
    r.y = acc.y * inv + b4.y; r.y = r.y > 0.f ? r.y : out_slope * r.y;
    r.z = acc.z * inv + b4.z; r.z = r.z > 0.f ? r.z : out_slope * r.z;
    r.w = acc.w * inv + b4.w; r.w = r.w > 0.f ? r.w : out_slope * r.w;
    reinterpret_cast<float4*>(out + ((size_t)nid * H + h) * C)[lane] = r;
}

// ---------------- graph pooling: one block per graph, no atomics ----------------
// batch is sorted -> binary-search the node range of each graph; thread c owns channel c.
__global__ __launch_bounds__(NHID)
void pool_graph_kernel(const float* __restrict__ x, const int* __restrict__ batch,
                       float* __restrict__ pool) {
    int gph = blockIdx.x;
    int tid = threadIdx.x;        // 0..127 = channel
    __shared__ int s_lo, s_hi;
    if (tid == 0) {
        int lo = 0, hi = N_NODES;
        while (lo < hi) { int mid = (lo + hi) >> 1; if (batch[mid] < gph) lo = mid + 1; else hi = mid; }
        s_lo = lo;
        lo = 0; hi = N_NODES;
        while (lo < hi) { int mid = (lo + hi) >> 1; if (batch[mid] < gph + 1) lo = mid + 1; else hi = mid; }
        s_hi = lo;
    }
    __syncthreads();
    int lo = s_lo, hi = s_hi;
    float m = -FLT_MAX;
    int n = lo;
    for (; n + 3 < hi; n += 4) {
        float v0 = x[(size_t)(n + 0) * NHID + tid];
        float v1 = x[(size_t)(n + 1) * NHID + tid];
        float v2 = x[(size_t)(n + 2) * NHID + tid];
        float v3 = x[(size_t)(n + 3) * NHID + tid];
        m = fmaxf(m, fmaxf(fmaxf(v0, v1), fmaxf(v2, v3)));
    }
    for (; n < hi; n++) m = fmaxf(m, x[(size_t)n * NHID + tid]);
    pool[gph * NHID + tid] = m;
}

// ---------------- launch ----------------
static inline float* symf(const void* sym) {
    void* p = nullptr; cudaGetSymbolAddress(&p, sym); return (float*)p;
}
static inline int* symi(const void* sym) {
    void* p = nullptr; cudaGetSymbolAddress(&p, sym); return (int*)p;
}

extern "C" void kernel_launch(void* const* d_in, const int* in_sizes, int n_in,
                              void* d_out, int out_size) {
    const float* x      = (const float*)d_in[0];
    const int*   eidx   = (const int*)  d_in[1];
    const int*   batch  = (const int*)  d_in[2];
    const float* fc1_w  = (const float*)d_in[3];
    const float* fc1_b  = (const float*)d_in[4];
    const float* w1     = (const float*)d_in[5];
    const float* att_l1 = (const float*)d_in[6];
    const float* att_r1 = (const float*)d_in[7];
    const float* b1     = (const float*)d_in[8];
    const float* w2     = (const float*)d_in[9];
    const float* att_l2 = (const float*)d_in[10];
    const float* att_r2 = (const float*)d_in[11];
    const float* b2     = (const float*)d_in[12];
    const float* fc2_w  = (const float*)d_in[13];
    const float* fc2_b  = (const float*)d_in[14];
    float* out = (float*)d_out;

    const int* e_src = eidx;
    const int* e_dst = eidx + N_EDGES;

    float* h0 = symf(g_h0); float* f1 = symf(g_f1); float* o1 = symf(g_o1);
    float* f2 = symf(g_f2); float* o2 = symf(g_o2); float* pool = symf(g_pool);
    float* aldot = symf(g_aldot); float* ardot = symf(g_ardot);
    int* deg = symi(g_deg); int* rowptr = symi(g_rowptr);
    int* cursor = symi(g_cursor); int* esrc = symi(g_esrc);

    zero_int_kernel<<<(N_NODES + 255) / 256, 256>>>(deg, N_NODES);                     // 0
    hist_kernel<<<(N_EDGES + 255) / 256, 256>>>(e_dst, deg, N_EDGES);                  // 1

    // GEMM1: h0 = leaky(x @ fc1_w + fc1_b)  [20000,300]x[300,128]  BM=64
    {
        dim3 grid(NHID / 128, (N_NODES + 63) / 64);
        gemm_tf32_kernel<64><<<grid, 128>>>(x, fc1_w, fc1_b, h0, N_NODES, NHID, N_IN, 0.01f, 1); // 2
    }
    // GEMM2: f1 = h0 @ w1   [20000,128]x[128,512]  (profiled slot 3, BM=128 control)
    {
        dim3 grid(HEADS * NHID / 128, (N_NODES + 127) / 128);
        gemm_tf32_kernel<128><<<grid, 256>>>(h0, w1, nullptr, f1, N_NODES, HEADS * NHID, NHID, 0.f, 0); // 3
    }

    scan_kernel<<<1, 1024>>>(deg, rowptr, cursor);                                     // 4
    scatter_kernel<<<(N_EDGES + 255) / 256, 256>>>(e_src, e_dst, cursor, esrc, N_EDGES); // 5

    {
        int warps = N_NODES * HEADS;
        attdot_kernel<HEADS><<<(warps * 32 + 255) / 256, 256>>>(f1, att_l1, att_r1, aldot, ardot); // 6
    }
    // Aggregation layer 1
    {
        int warps = N_NODES * HEADS;
        agg_kernel<HEADS><<<(warps * 32 + 255) / 256, 256>>>(f1, aldot, ardot, b1,
                                                             rowptr, esrc, o1, 0.01f); // 7
    }
    // GEMM3: f2 = o1 @ w2   [20000,512]x[512,128]  BM=64
    {
        dim3 grid(NHID / 128, (N_NODES + 63) / 64);
        gemm_tf32_kernel<64><<<grid, 128>>>(o1, w2, nullptr, f2, N_NODES, NHID, HEADS * NHID, 0.f, 0); // 8
    }
    {
        int warps = N_NODES;
        attdot_kernel<1><<<(warps * 32 + 255) / 256, 256>>>(f2, att_l2, att_r2, aldot, ardot); // 9
    }
    // Aggregation layer 2
    {
        int warps = N_NODES;
        agg_kernel<1><<<(warps * 32 + 255) / 256, 256>>>(f2, aldot, ardot, b2,
                                                         rowptr, esrc, o2, 0.01f);     // 10
    }
    // Pooling: per-graph block, no atomics, no init
    pool_graph_kernel<<<NUM_GRAPHS, NHID>>>(o2, batch, pool);                          // 11

    // GEMM4: out = pool @ fc2_w + fc2_b   [128,128]x[128,768]  BM=64 -> 12 blocks
    {
        dim3 grid(NOUT / 128, (NUM_GRAPHS + 63) / 64);
        gemm_tf32_kernel<64><<<grid, 128>>>(pool, fc2_w, fc2_b, out, NUM_GRAPHS, NOUT, NHID, 0.f, 0); // 12
    }
}

// round 13
// speedup vs baseline: 1.0666x; 1.0132x over previous
#include <cuda_runtime.h>
#include <cuda_bf16.h>
#include <cfloat>
#include <math.h>

// ---------------- problem constants ----------------
#define N_NODES   20000
#define N_EDGES   160000
#define N_IN      300
#define NHID      128
#define HEADS     4
#define NOUT      768
#define NUM_GRAPHS 128

typedef unsigned long long ull;

// ---------------- scratch ----------------
__device__ float g_h0[N_NODES * NHID];
__device__ float g_f1[N_NODES * HEADS * NHID];
__device__ float g_o1[N_NODES * HEADS * NHID];
__device__ float g_f2[N_NODES * NHID];
__device__ float g_o2[N_NODES * NHID];
__device__ float g_aldot[N_NODES * HEADS];
__device__ float g_ardot[N_NODES * HEADS];
__device__ int   g_deg[N_NODES];          // zero-initialized; re-zeroed by scatter each call
__device__ int   g_rowptr[N_NODES + 1];
__device__ int   g_cursor[N_NODES];
__device__ int   g_esrc[N_EDGES];
__device__ float g_pool[NUM_GRAPHS * NHID];

// ---------------- tf32 helpers ----------------
__device__ __forceinline__ unsigned f2tf32(float f) {
    unsigned u;
    asm("cvt.rna.tf32.f32 %0, %1;" : "=r"(u) : "f"(f));
    return u;
}
__device__ __forceinline__ void mma_tf32(float& d0, float& d1, float& d2, float& d3,
                                         unsigned a0, unsigned a1, unsigned a2, unsigned a3,
                                         unsigned b0, unsigned b1) {
    asm("mma.sync.aligned.m16n8k8.row.col.f32.tf32.tf32.f32 "
        "{%0,%1,%2,%3}, {%4,%5,%6,%7}, {%8,%9}, {%0,%1,%2,%3};"
        : "+f"(d0), "+f"(d1), "+f"(d2), "+f"(d3)
        : "r"(a0), "r"(a1), "r"(a2), "r"(a3), "r"(b0), "r"(b1));
}

__device__ __forceinline__ float dot4(float4 a, float4 b) {
    return a.x * b.x + a.y * b.y + a.z * b.z + a.w * b.w;
}

// ---------------- CSR build ----------------
__global__ void hist_kernel(const int* __restrict__ dst, int* __restrict__ deg, int E) {
    int i = blockIdx.x * blockDim.x + threadIdx.x;
    if (i < E) atomicAdd(&deg[dst[i]], 1);
}

__global__ void scan_kernel(const int* __restrict__ deg, int* __restrict__ rowptr,
                            int* __restrict__ cursor) {
    __shared__ int sh[1024];
    const int PER = 20;
    int tid = threadIdx.x;
    int base = tid * PER;
    int loc[PER];
    int s = 0;
    #pragma unroll
    for (int i = 0; i < PER; i++) {
        int idx = base + i;
        int v = (idx < N_NODES) ? deg[idx] : 0;
        loc[i] = s;
        s += v;
    }
    sh[tid] = s;
    __syncthreads();
    #pragma unroll
    for (int off = 1; off < 1024; off <<= 1) {
        int t = (tid >= off) ? sh[tid - off] : 0;
        __syncthreads();
        sh[tid] += t;
        __syncthreads();
    }
    int prev = (tid > 0) ? sh[tid - 1] : 0;
    #pragma unroll
    for (int i = 0; i < PER; i++) {
        int idx = base + i;
        if (idx < N_NODES) {
            int v = prev + loc[i];
            rowptr[idx] = v;
            cursor[idx] = v;
        }
    }
    if (tid == 1023) rowptr[N_NODES] = sh[1023];
}

// scatter also re-zeroes deg (consumed by scan already; leaves it 0 for next call)
__global__ void scatter_kernel(const int* __restrict__ src, const int* __restrict__ dst,
                               int* __restrict__ cursor, int* __restrict__ esrc,
                               int* __restrict__ deg, int E) {
    int i = blockIdx.x * blockDim.x + threadIdx.x;
    if (i < N_NODES) deg[i] = 0;
    if (i < E) {
        int d = dst[i];
        int p = atomicAdd(&cursor[d], 1);
        esrc[p] = src[i];
    }
}

// ---------------- tf32 tensor-core GEMM, double-buffered, A fragment-permuted ----------------
// THREADS = 2*BM. Warp tile 64x32; BM=128: 8 warps (2x4); BM=64: 4 warps (1x4).
// A smem columns permuted within aligned 16-blocks: perm(m)=(m&~15)|((m&7)<<1)|((m>>3)&1)
// so each thread's (g, g+8) A-fragment pair is one LDS.64.
template<int BM>
__global__ __launch_bounds__(2 * BM)
void gemm_tf32_kernel(const float* __restrict__ A, const float* __restrict__ B,
                      const float* __restrict__ bias, float* __restrict__ C,
                      int M, int N, int K, float slope, int act) {
    const int BK = 16;
    const int ASTR = BM + 8;
    const int THREADS = 2 * BM;
    const int BROWS = THREADS / 16;
    const int BPASS = 16 / BROWS;
    __shared__ __align__(16) unsigned As[2][BK * ASTR];
    __shared__ __align__(16) unsigned Bs[2][32 * 33 * 2];

    int tid = threadIdx.x;
    int lane = tid & 31;
    int wid = tid >> 5;
    int warpM = wid >> 2;
    int warpN = wid & 3;
    int bm = blockIdx.y * BM, bn = blockIdx.x * 128;
    int g = lane >> 2, c = lane & 3;

    float acc[4][4][4];
    #pragma unroll
    for (int mi = 0; mi < 4; mi++)
        #pragma unroll
        for (int ni = 0; ni < 4; ni++)
            #pragma unroll
            for (int r = 0; r < 4; r++) acc[mi][ni][r] = 0.f;

    int la_m = tid >> 1;
    int la_k = (tid & 1) * 8;
    int gmA = bm + la_m;
    int pa_m = (la_m & ~15) | ((la_m & 7) << 1) | ((la_m >> 3) & 1);   // permuted column
    int lbn = (tid & 15) * 8;
    int b_nb = tid & 15;

    float4 pa0, pa1;
    float pbv[BPASS][8];

    int nT = (K + BK - 1) / BK;

    auto load_tile = [&](int k0) {
        pa0 = make_float4(0.f, 0.f, 0.f, 0.f);
        pa1 = make_float4(0.f, 0.f, 0.f, 0.f);
        int gk0 = k0 + la_k;
        if (gmA < M && gk0 < K)
            pa0 = *reinterpret_cast<const float4*>(&A[(size_t)gmA * K + gk0]);
        if (gmA < M && gk0 + 4 < K)
            pa1 = *reinterpret_cast<const float4*>(&A[(size_t)gmA * K + gk0 + 4]);
        #pragma unroll
        for (int pass = 0; pass < BPASS; pass++) {
            int lbk = (tid >> 4) + pass * BROWS;
            int gk = k0 + lbk;
            float4 v0 = make_float4(0.f, 0.f, 0.f, 0.f);
            float4 v1 = make_float4(0.f, 0.f, 0.f, 0.f);
            if (gk < K) {
                v0 = *reinterpret_cast<const float4*>(&B[(size_t)gk * N + bn + lbn]);
                v1 = *reinterpret_cast<const float4*>(&B[(size_t)gk * N + bn + lbn + 4]);
            }
            pbv[pass][0] = v0.x; pbv[pass][1] = v0.y; pbv[pass][2] = v0.z; pbv[pass][3] = v0.w;
            pbv[pass][4] = v1.x; pbv[pass][5] = v1.y; pbv[pass][6] = v1.z; pbv[pass][7] = v1.w;
        }
    };
    auto store_tile = [&](int buf) {
        As[buf][(la_k + 0) * ASTR + pa_m] = f2tf32(pa0.x);
        As[buf][(la_k + 1) * ASTR + pa_m] = f2tf32(pa0.y);
        As[buf][(la_k + 2) * ASTR + pa_m] = f2tf32(pa0.z);
        As[buf][(la_k + 3) * ASTR + pa_m] = f2tf32(pa0.w);
        As[buf][(la_k + 4) * ASTR + pa_m] = f2tf32(pa1.x);
        As[buf][(la_k + 5) * ASTR + pa_m] = f2tf32(pa1.y);
        As[buf][(la_k + 6) * ASTR + pa_m] = f2tf32(pa1.z);
        As[buf][(la_k + 7) * ASTR + pa_m] = f2tf32(pa1.w);
        #pragma unroll
        for (int pass = 0; pass < BPASS; pass++) {
            int lbk = (tid >> 4) + pass * BROWS;
            int b_kb = lbk >> 3;
            int b_c = lbk & 3;
            int b_half = (lbk & 7) >> 2;
            int grp = b_kb * 16 + b_nb;
            #pragma unroll
            for (int j = 0; j < 8; j++) {
                int u = grp * 33 + j * 4 + b_c;
                Bs[buf][2 * u + b_half] = f2tf32(pbv[pass][j]);
            }
        }
    };

    load_tile(0);
    store_tile(0);
    __syncthreads();

    for (int t = 0; t < nT; t++) {
        int buf = t & 1;
        bool more = (t + 1) < nT;
        if (more) load_tile((t + 1) * BK);

        #pragma unroll
        for (int kb = 0; kb < 2; kb++) {
            unsigned af[4][4];
            int r0 = (kb * 8 + c) * ASTR;
            int r1 = (kb * 8 + c + 4) * ASTR;
            #pragma unroll
            for (int mi = 0; mi < 4; mi++) {
                int m0 = warpM * 64 + mi * 16;
                uint2 p0 = *reinterpret_cast<const uint2*>(&As[buf][r0 + m0 + 2 * g]);
                uint2 p1 = *reinterpret_cast<const uint2*>(&As[buf][r1 + m0 + 2 * g]);
                af[mi][0] = p0.x;  // m = m0 + g
                af[mi][1] = p0.y;  // m = m0 + g + 8
                af[mi][2] = p1.x;
                af[mi][3] = p1.y;
            }
            unsigned bf[4][2];
            #pragma unroll
            for (int ni = 0; ni < 4; ni++) {
                int grp = kb * 16 + warpN * 4 + ni;
                uint2 tt = *reinterpret_cast<const uint2*>(&Bs[buf][2 * (grp * 33 + lane)]);
                bf[ni][0] = tt.x;
                bf[ni][1] = tt.y;
            }
            #pragma unroll
            for (int mi = 0; mi < 4; mi++)
                #pragma unroll
                for (int ni = 0; ni < 4; ni++)
                    mma_tf32(acc[mi][ni][0], acc[mi][ni][1], acc[mi][ni][2], acc[mi][ni][3],
                             af[mi][0], af[mi][1], af[mi][2], af[mi][3],
                             bf[ni][0], bf[ni][1]);
        }

        if (more) store_tile(1 - buf);
        __syncthreads();
    }

    #pragma unroll
    for (int mi = 0; mi < 4; mi++) {
        int row0 = bm + warpM * 64 + mi * 16 + g;
        #pragma unroll
        for (int ni = 0; ni < 4; ni++) {
            int col = bn + warpN * 32 + ni * 8 + c * 2;
            float bv0 = bias ? bias[col] : 0.f;
            float bv1 = bias ? bias[col + 1] : 0.f;
            if (row0 < M) {
                float x0 = acc[mi][ni][0] + bv0;
                float x1 = acc[mi][ni][1] + bv1;
                if (act) {
                    x0 = x0 > 0.f ? x0 : slope * x0;
                    x1 = x1 > 0.f ? x1 : slope * x1;
                }
                *reinterpret_cast<float2*>(&C[(size_t)row0 * N + col]) = make_float2(x0, x1);
            }
            int row1 = row0 + 8;
            if (row1 < M) {
                float x2 = acc[mi][ni][2] + bv0;
                float x3 = acc[mi][ni][3] + bv1;
                if (act) {
                    x2 = x2 > 0.f ? x2 : slope * x2;
                    x3 = x3 > 0.f ? x3 : slope * x3;
                }
                *reinterpret_cast<float2*>(&C[(size_t)row1 * N + col]) = make_float2(x2, x3);
            }
        }
    }
}

// ---------------- precompute attention dots ----------------
template<int H>
__global__ void attdot_kernel(const float* __restrict__ feat,
                              const float* __restrict__ attL, const float* __restrict__ attR,
                              float* __restrict__ aldot, float* __restrict__ ardot) {
    int warp = (blockIdx.x * blockDim.x + threadIdx.x) >> 5;
    int lane = threadIdx.x & 31;
    if (warp >= N_NODES * H) return;
    int nid = warp / H, h = warp % H;
    float4 x = reinterpret_cast<const float4*>(feat + ((size_t)nid * H + h) * NHID)[lane];
    float4 aL = reinterpret_cast<const float4*>(attL + h * NHID)[lane];
    float4 aR = reinterpret_cast<const float4*>(attR + h * NHID)[lane];
    float al = dot4(x, aL);
    float ar = dot4(x, aR);
    #pragma unroll
    for (int o = 16; o; o >>= 1) {
        al += __shfl_xor_sync(0xffffffffu, al, o);
        ar += __shfl_xor_sync(0xffffffffu, ar, o);
    }
    if (lane == 0) { aldot[warp] = al; ardot[warp] = ar; }
}

// ---------------- SuperGAT aggregation: one warp per (node, head), 4-edge unroll ----------------
template<int H>
__global__ void agg_kernel(const float* __restrict__ feat,
                           const float* __restrict__ aldot, const float* __restrict__ ardot,
                           const float* __restrict__ bias,
                           const int* __restrict__ rowptr, const int* __restrict__ esrc,
                           float* __restrict__ out, float out_slope) {
    const int C = NHID;
    int warp = (blockIdx.x * blockDim.x + threadIdx.x) >> 5;
    int lane = threadIdx.x & 31;
    if (warp >= N_NODES * H) return;
    int nid = warp / H;
    int h   = warp % H;

    float4 xi = reinterpret_cast<const float4*>(feat + ((size_t)nid * H + h) * C)[lane];
    float ar = ardot[warp];

    float m = -INFINITY, s = 0.f;
    float4 acc = make_float4(0.f, 0.f, 0.f, 0.f);

    int e0 = rowptr[nid], e1 = rowptr[nid + 1];
    int e = e0;
    for (; e + 3 < e1; e += 4) {
        int s0 = esrc[e], s1 = esrc[e + 1], s2 = esrc[e + 2], s3 = esrc[e + 3];
        float4 xj0 = reinterpret_cast<const float4*>(feat + ((size_t)s0 * H + h) * C)[lane];
        float4 xj1 = reinterpret_cast<const float4*>(feat + ((size_t)s1 * H + h) * C)[lane];
        float4 xj2 = reinterpret_cast<const float4*>(feat + ((size_t)s2 * H + h) * C)[lane];
        float4 xj3 = reinterpret_cast<const float4*>(feat + ((size_t)s3 * H + h) * C)[lane];
        float lg0 = dot4(xi, xj0), lg1 = dot4(xi, xj1);
        float lg2 = dot4(xi, xj2), lg3 = dot4(xi, xj3);
        #pragma unroll
        for (int o = 16; o; o >>= 1) {
            lg0 += __shfl_xor_sync(0xffffffffu, lg0, o);
            lg1 += __shfl_xor_sync(0xffffffffu, lg1, o);
            lg2 += __shfl_xor_sync(0xffffffffu, lg2, o);
            lg3 += __shfl_xor_sync(0xffffffffu, lg3, o);
        }
        float a0 = (aldot[s0 * H + h] + ar) * (1.f / (1.f + __expf(-lg0)));
        float a1 = (aldot[s1 * H + h] + ar) * (1.f / (1.f + __expf(-lg1)));
        float a2 = (aldot[s2 * H + h] + ar) * (1.f / (1.f + __expf(-lg2)));
        float a3 = (aldot[s3 * H + h] + ar) * (1.f / (1.f + __expf(-lg3)));
        a0 = a0 > 0.f ? a0 : 0.2f * a0;
        a1 = a1 > 0.f ? a1 : 0.2f * a1;
        a2 = a2 > 0.f ? a2 : 0.2f * a2;
        a3 = a3 > 0.f ? a3 : 0.2f * a3;
        float mx = fmaxf(fmaxf(a0, a1), fmaxf(a2, a3));
        float mn = fmaxf(m, mx);
        float sc = __expf(m - mn);
        float w0 = __expf(a0 - mn), w1 = __expf(a1 - mn);
        float w2 = __expf(a2 - mn), w3 = __expf(a3 - mn);
        s = s * sc + w0 + w1 + w2 + w3;
        acc.x = acc.x * sc + w0 * xj0.x + w1 * xj1.x + w2 * xj2.x + w3 * xj3.x;
        acc.y = acc.y * sc + w0 * xj0.y + w1 * xj1.y + w2 * xj2.y + w3 * xj3.y;
        acc.z = acc.z * sc + w0 * xj0.z + w1 * xj1.z + w2 * xj2.z + w3 * xj3.z;
        acc.w = acc.w * sc + w0 * xj0.w + w1 * xj1.w + w2 * xj2.w + w3 * xj3.w;
        m = mn;
    }
    for (; e < e1; e++) {
        int sn = esrc[e];
        float4 xj = reinterpret_cast<const float4*>(feat + ((size_t)sn * H + h) * C)[lane];
        float lg = dot4(xi, xj);
        #pragma unroll
        for (int o = 16; o; o >>= 1) lg += __shfl_xor_sync(0xffffffffu, lg, o);
        float al = aldot[sn * H + h];
        float a = (al + ar) * (1.f / (1.f + __expf(-lg)));
        a = a > 0.f ? a : 0.2f * a;
        float mn = fmaxf(m, a);
        float sc = __expf(m - mn);
        float w = __expf(a - mn);
        s = s * sc + w;
        acc.x = acc.x * sc + w * xj.x;
        acc.y = acc.y * sc + w * xj.y;
        acc.z = acc.z * sc + w * xj.z;
        acc.w = acc.w * sc + w * xj.w;
        m = mn;
    }
    float inv = 1.f / (s + 1e-16f);
    float4 b4 = reinterpret_cast<const float4*>(bias + h * C)[lane];
    float4 r;
    r.x = acc.x * inv + b4.x; r.x = r.x > 0.f ? r.x : out_slope * r.x;
    r.y = acc.y * inv + b4.y; r.y = r.y > 0.f ? r.y : out_slope * r.y;
    r.z = acc.z * inv + b4.z; r.z = r.z > 0.f ? r.z : out_slope * r.z;
    r.w = acc.w * inv + b4.w; r.w = r.w > 0.f ? r.w : out_slope * r.w;
    reinterpret_cast<float4*>(out + ((size_t)nid * H + h) * C)[lane] = r;
}

// ---------------- graph pooling: one block per graph, no atomics ----------------
__global__ __launch_bounds__(NHID)
void pool_graph_kernel(const float* __restrict__ x, const int* __restrict__ batch,
                       float* __restrict__ pool) {
    int gph = blockIdx.x;
    int tid = threadIdx.x;
    __shared__ int s_lo, s_hi;
    if (tid == 0) {
        int lo = 0, hi = N_NODES;
        while (lo < hi) { int mid = (lo + hi) >> 1; if (batch[mid] < gph) lo = mid + 1; else hi = mid; }
        s_lo = lo;
        lo = 0; hi = N_NODES;
        while (lo < hi) { int mid = (lo + hi) >> 1; if (batch[mid] < gph + 1) lo = mid + 1; else hi = mid; }
        s_hi = lo;
    }
    __syncthreads();
    int lo = s_lo, hi = s_hi;
    float m = -FLT_MAX;
    int n = lo;
    for (; n + 3 < hi; n += 4) {
        float v0 = x[(size_t)(n + 0) * NHID + tid];
        float v1 = x[(size_t)(n + 1) * NHID + tid];
        float v2 = x[(size_t)(n + 2) * NHID + tid];
        float v3 = x[(size_t)(n + 3) * NHID + tid];
        m = fmaxf(m, fmaxf(fmaxf(v0, v1), fmaxf(v2, v3)));
    }
    for (; n < hi; n++) m = fmaxf(m, x[(size_t)n * NHID + tid]);
    pool[gph * NHID + tid] = m;
}

// ---------------- launch ----------------
static inline float* symf(const void* sym) {
    void* p = nullptr; cudaGetSymbolAddress(&p, sym); return (float*)p;
}
static inline int* symi(const void* sym) {
    void* p = nullptr; cudaGetSymbolAddress(&p, sym); return (int*)p;
}

extern "C" void kernel_launch(void* const* d_in, const int* in_sizes, int n_in,
                              void* d_out, int out_size) {
    const float* x      = (const float*)d_in[0];
    const int*   eidx   = (const int*)  d_in[1];
    const int*   batch  = (const int*)  d_in[2];
    const float* fc1_w  = (const float*)d_in[3];
    const float* fc1_b  = (const float*)d_in[4];
    const float* w1     = (const float*)d_in[5];
    const float* att_l1 = (const float*)d_in[6];
    const float* att_r1 = (const float*)d_in[7];
    const float* b1     = (const float*)d_in[8];
    const float* w2     = (const float*)d_in[9];
    const float* att_l2 = (const float*)d_in[10];
    const float* att_r2 = (const float*)d_in[11];
    const float* b2     = (const float*)d_in[12];
    const float* fc2_w  = (const float*)d_in[13];
    const float* fc2_b  = (const float*)d_in[14];
    float* out = (float*)d_out;

    const int* e_src = eidx;
    const int* e_dst = eidx + N_EDGES;

    float* h0 = symf(g_h0); float* f1 = symf(g_f1); float* o1 = symf(g_o1);
    float* f2 = symf(g_f2); float* o2 = symf(g_o2); float* pool = symf(g_pool);
    float* aldot = symf(g_aldot); float* ardot = symf(g_ardot);
    int* deg = symi(g_deg); int* rowptr = symi(g_rowptr);
    int* cursor = symi(g_cursor); int* esrc = symi(g_esrc);

    hist_kernel<<<(N_EDGES + 255) / 256, 256>>>(e_dst, deg, N_EDGES);                  // 0

    // GEMM1: h0 = leaky(x @ fc1_w + fc1_b)  BM=64
    {
        dim3 grid(NHID / 128, (N_NODES + 63) / 64);
        gemm_tf32_kernel<64><<<grid, 128>>>(x, fc1_w, fc1_b, h0, N_NODES, NHID, N_IN, 0.01f, 1); // 1
    }
    scan_kernel<<<1, 1024>>>(deg, rowptr, cursor);                                     // 2
    // GEMM2: f1 = h0 @ w1  (profiled slot 3, BM=128)
    {
        dim3 grid(HEADS * NHID / 128, (N_NODES + 127) / 128);
        gemm_tf32_kernel<128><<<grid, 256>>>(h0, w1, nullptr, f1, N_NODES, HEADS * NHID, NHID, 0.f, 0); // 3
    }
    scatter_kernel<<<(N_EDGES + 255) / 256, 256>>>(e_src, e_dst, cursor, esrc, deg, N_EDGES); // 4

    {
        int warps = N_NODES * HEADS;
        attdot_kernel<HEADS><<<(warps * 32 + 255) / 256, 256>>>(f1, att_l1, att_r1, aldot, ardot); // 5
    }
    // Aggregation layer 1
    {
        int warps = N_NODES * HEADS;
        agg_kernel<HEADS><<<(warps * 32 + 255) / 256, 256>>>(f1, aldot, ardot, b1,
                                                             rowptr, esrc, o1, 0.01f); // 6
    }
    // GEMM3: f2 = o1 @ w2  BM=64
    {
        dim3 grid(NHID / 128, (N_NODES + 63) / 64);
        gemm_tf32_kernel<64><<<grid, 128>>>(o1, w2, nullptr, f2, N_NODES, NHID, HEADS * NHID, 0.f, 0); // 7
    }
    {
        int warps = N_NODES;
        attdot_kernel<1><<<(warps * 32 + 255) / 256, 256>>>(f2, att_l2, att_r2, aldot, ardot); // 8
    }
    // Aggregation layer 2
    {
        int warps = N_NODES;
        agg_kernel<1><<<(warps * 32 + 255) / 256, 256>>>(f2, aldot, ardot, b2,
                                                         rowptr, esrc, o2, 0.01f);     // 9
    }
    // Pooling
    pool_graph_kernel<<<NUM_GRAPHS, NHID>>>(o2, batch, pool);                          // 10

    // GEMM4: out = pool @ fc2_w + fc2_b  BM=64
    {
        dim3 grid(NOUT / 128, (NUM_GRAPHS + 63) / 64);
        gemm_tf32_kernel<64><<<grid, 128>>>(pool, fc2_w, fc2_b, out, NUM_GRAPHS, NOUT, NHID, 0.f, 0); // 11
    }
}

// round 14
// speedup vs baseline: 1.0989x; 1.0303x over previous
#include <cuda_runtime.h>
#include <cuda_bf16.h>
#include <cfloat>
#include <math.h>

// ---------------- problem constants ----------------
#define N_NODES   20000
#define N_EDGES   160000
#define N_IN      300
#define NHID      128
#define HEADS     4
#define NOUT      768
#define NUM_GRAPHS 128

typedef unsigned long long ull;

// ---------------- scratch ----------------
__device__ float g_h0[N_NODES * NHID];
__device__ float g_f1[N_NODES * HEADS * NHID];
__device__ float g_o1[N_NODES * HEADS * NHID];
__device__ float g_f2[N_NODES * NHID];
__device__ float g_o2[N_NODES * NHID];
__device__ float g_aldot[N_NODES * HEADS];
__device__ float g_ardot[N_NODES * HEADS];
__device__ int   g_deg[N_NODES];          // zero-initialized; re-zeroed by scatter each call
__device__ int   g_rowptr[N_NODES + 1];
__device__ int   g_cursor[N_NODES];
__device__ int   g_esrc[N_EDGES];
__device__ float g_pool[NUM_GRAPHS * NHID];

// ---------------- tf32 helpers ----------------
__device__ __forceinline__ unsigned f2tf32(float f) {
    unsigned u;
    asm("cvt.rna.tf32.f32 %0, %1;" : "=r"(u) : "f"(f));
    return u;
}
__device__ __forceinline__ void mma_tf32(float& d0, float& d1, float& d2, float& d3,
                                         unsigned a0, unsigned a1, unsigned a2, unsigned a3,
                                         unsigned b0, unsigned b1) {
    asm("mma.sync.aligned.m16n8k8.row.col.f32.tf32.tf32.f32 "
        "{%0,%1,%2,%3}, {%4,%5,%6,%7}, {%8,%9}, {%0,%1,%2,%3};"
        : "+f"(d0), "+f"(d1), "+f"(d2), "+f"(d3)
        : "r"(a0), "r"(a1), "r"(a2), "r"(a3), "r"(b0), "r"(b1));
}

__device__ __forceinline__ float dot4(float4 a, float4 b) {
    return a.x * b.x + a.y * b.y + a.z * b.z + a.w * b.w;
}

// ---------------- CSR build ----------------
__global__ void hist_kernel(const int* __restrict__ dst, int* __restrict__ deg, int E) {
    int i = blockIdx.x * blockDim.x + threadIdx.x;
    if (i < E) atomicAdd(&deg[dst[i]], 1);
}

__global__ void scan_kernel(const int* __restrict__ deg, int* __restrict__ rowptr,
                            int* __restrict__ cursor) {
    __shared__ int sh[1024];
    const int PER = 20;
    int tid = threadIdx.x;
    int base = tid * PER;
    int loc[PER];
    int s = 0;
    #pragma unroll
    for (int i = 0; i < PER; i++) {
        int idx = base + i;
        int v = (idx < N_NODES) ? deg[idx] : 0;
        loc[i] = s;
        s += v;
    }
    sh[tid] = s;
    __syncthreads();
    #pragma unroll
    for (int off = 1; off < 1024; off <<= 1) {
        int t = (tid >= off) ? sh[tid - off] : 0;
        __syncthreads();
        sh[tid] += t;
        __syncthreads();
    }
    int prev = (tid > 0) ? sh[tid - 1] : 0;
    #pragma unroll
    for (int i = 0; i < PER; i++) {
        int idx = base + i;
        if (idx < N_NODES) {
            int v = prev + loc[i];
            rowptr[idx] = v;
            cursor[idx] = v;
        }
    }
    if (tid == 1023) rowptr[N_NODES] = sh[1023];
}

__global__ void scatter_kernel(const int* __restrict__ src, const int* __restrict__ dst,
                               int* __restrict__ cursor, int* __restrict__ esrc,
                               int* __restrict__ deg, int E) {
    int i = blockIdx.x * blockDim.x + threadIdx.x;
    if (i < N_NODES) deg[i] = 0;
    if (i < E) {
        int d = dst[i];
        int p = atomicAdd(&cursor[d], 1);
        esrc[p] = src[i];
    }
}

// ---------------- tf32 tensor-core GEMM, double-buffered, fused attdot epilogue ----------------
// THREADS = 2*BM. Warp tile 64x32; BM=128: 8 warps (2x4); BM=64: 4 warps (1x4).
// If aldot != nullptr: each BNx column block is one attention head (head = blockIdx.x when N=H*128),
// and the epilogue computes aldot[(row)*H + head] = dot(C_row, attL_head), same for ar.
template<int BM, int H>
__global__ __launch_bounds__(2 * BM)
void gemm_tf32_kernel(const float* __restrict__ A, const float* __restrict__ B,
                      const float* __restrict__ bias, float* __restrict__ C,
                      int M, int N, int K, float slope, int act,
                      const float* __restrict__ attL, const float* __restrict__ attR,
                      float* __restrict__ aldot, float* __restrict__ ardot) {
    const int BK = 16;
    const int ASTR = BM + 8;
    const int THREADS = 2 * BM;
    const int BROWS = THREADS / 16;
    const int BPASS = 16 / BROWS;
    __shared__ __align__(16) unsigned As[2][BK * ASTR];
    __shared__ __align__(16) unsigned Bs[2][32 * 33 * 2];
    __shared__ float redAL[BM][4];
    __shared__ float redAR[BM][4];

    int tid = threadIdx.x;
    int lane = tid & 31;
    int wid = tid >> 5;
    int warpM = wid >> 2;
    int warpN = wid & 3;
    int bm = blockIdx.y * BM, bn = blockIdx.x * 128;
    int g = lane >> 2, c = lane & 3;

    float acc[4][4][4];
    #pragma unroll
    for (int mi = 0; mi < 4; mi++)
        #pragma unroll
        for (int ni = 0; ni < 4; ni++)
            #pragma unroll
            for (int r = 0; r < 4; r++) acc[mi][ni][r] = 0.f;

    int la_m = tid >> 1;
    int la_k = (tid & 1) * 8;
    int gmA = bm + la_m;
    int pa_m = (la_m & ~15) | ((la_m & 7) << 1) | ((la_m >> 3) & 1);
    int lbn = (tid & 15) * 8;
    int b_nb = tid & 15;

    float4 pa0, pa1;
    float pbv[BPASS][8];

    int nT = (K + BK - 1) / BK;

    auto load_tile = [&](int k0) {
        pa0 = make_float4(0.f, 0.f, 0.f, 0.f);
        pa1 = make_float4(0.f, 0.f, 0.f, 0.f);
        int gk0 = k0 + la_k;
        if (gmA < M && gk0 < K)
            pa0 = *reinterpret_cast<const float4*>(&A[(size_t)gmA * K + gk0]);
        if (gmA < M && gk0 + 4 < K)
            pa1 = *reinterpret_cast<const float4*>(&A[(size_t)gmA * K + gk0 + 4]);
        #pragma unroll
        for (int pass = 0; pass < BPASS; pass++) {
            int lbk = (tid >> 4) + pass * BROWS;
            int gk = k0 + lbk;
            float4 v0 = make_float4(0.f, 0.f, 0.f, 0.f);
            float4 v1 = make_float4(0.f, 0.f, 0.f, 0.f);
            if (gk < K) {
                v0 = *reinterpret_cast<const float4*>(&B[(size_t)gk * N + bn + lbn]);
                v1 = *reinterpret_cast<const float4*>(&B[(size_t)gk * N + bn + lbn + 4]);
            }
            pbv[pass][0] = v0.x; pbv[pass][1] = v0.y; pbv[pass][2] = v0.z; pbv[pass][3] = v0.w;
            pbv[pass][4] = v1.x; pbv[pass][5] = v1.y; pbv[pass][6] = v1.z; pbv[pass][7] = v1.w;
        }
    };
    auto store_tile = [&](int buf) {
        As[buf][(la_k + 0) * ASTR + pa_m] = f2tf32(pa0.x);
        As[buf][(la_k + 1) * ASTR + pa_m] = f2tf32(pa0.y);
        As[buf][(la_k + 2) * ASTR + pa_m] = f2tf32(pa0.z);
        As[buf][(la_k + 3) * ASTR + pa_m] = f2tf32(pa0.w);
        As[buf][(la_k + 4) * ASTR + pa_m] = f2tf32(pa1.x);
        As[buf][(la_k + 5) * ASTR + pa_m] = f2tf32(pa1.y);
        As[buf][(la_k + 6) * ASTR + pa_m] = f2tf32(pa1.z);
        As[buf][(la_k + 7) * ASTR + pa_m] = f2tf32(pa1.w);
        #pragma unroll
        for (int pass = 0; pass < BPASS; pass++) {
            int lbk = (tid >> 4) + pass * BROWS;
            int b_kb = lbk >> 3;
            int b_c = lbk & 3;
            int b_half = (lbk & 7) >> 2;
            int grp = b_kb * 16 + b_nb;
            #pragma unroll
            for (int j = 0; j < 8; j++) {
                int u = grp * 33 + j * 4 + b_c;
                Bs[buf][2 * u + b_half] = f2tf32(pbv[pass][j]);
            }
        }
    };

    load_tile(0);
    store_tile(0);
    __syncthreads();

    for (int t = 0; t < nT; t++) {
        int buf = t & 1;
        bool more = (t + 1) < nT;
        if (more) load_tile((t + 1) * BK);

        #pragma unroll
        for (int kb = 0; kb < 2; kb++) {
            unsigned af[4][4];
            int r0 = (kb * 8 + c) * ASTR;
            int r1 = (kb * 8 + c + 4) * ASTR;
            #pragma unroll
            for (int mi = 0; mi < 4; mi++) {
                int m0 = warpM * 64 + mi * 16;
                uint2 p0 = *reinterpret_cast<const uint2*>(&As[buf][r0 + m0 + 2 * g]);
                uint2 p1 = *reinterpret_cast<const uint2*>(&As[buf][r1 + m0 + 2 * g]);
                af[mi][0] = p0.x;
                af[mi][1] = p0.y;
                af[mi][2] = p1.x;
                af[mi][3] = p1.y;
            }
            unsigned bf[4][2];
            #pragma unroll
            for (int ni = 0; ni < 4; ni++) {
                int grp = kb * 16 + warpN * 4 + ni;
                uint2 tt = *reinterpret_cast<const uint2*>(&Bs[buf][2 * (grp * 33 + lane)]);
                bf[ni][0] = tt.x;
                bf[ni][1] = tt.y;
            }
            #pragma unroll
            for (int mi = 0; mi < 4; mi++)
                #pragma unroll
                for (int ni = 0; ni < 4; ni++)
                    mma_tf32(acc[mi][ni][0], acc[mi][ni][1], acc[mi][ni][2], acc[mi][ni][3],
                             af[mi][0], af[mi][1], af[mi][2], af[mi][3],
                             bf[ni][0], bf[ni][1]);
        }

        if (more) store_tile(1 - buf);
        __syncthreads();
    }

    // ---- main epilogue: bias/act + store ----
    #pragma unroll
    for (int mi = 0; mi < 4; mi++) {
        int row0 = bm + warpM * 64 + mi * 16 + g;
        #pragma unroll
        for (int ni = 0; ni < 4; ni++) {
            int col = bn + warpN * 32 + ni * 8 + c * 2;
            float bv0 = bias ? bias[col] : 0.f;
            float bv1 = bias ? bias[col + 1] : 0.f;
            if (row0 < M) {
                float x0 = acc[mi][ni][0] + bv0;
                float x1 = acc[mi][ni][1] + bv1;
                if (act) {
                    x0 = x0 > 0.f ? x0 : slope * x0;
                    x1 = x1 > 0.f ? x1 : slope * x1;
                }
                *reinterpret_cast<float2*>(&C[(size_t)row0 * N + col]) = make_float2(x0, x1);
            }
            int row1 = row0 + 8;
            if (row1 < M) {
                float x2 = acc[mi][ni][2] + bv0;
                float x3 = acc[mi][ni][3] + bv1;
                if (act) {
                    x2 = x2 > 0.f ? x2 : slope * x2;
                    x3 = x3 > 0.f ? x3 : slope * x3;
                }
                *reinterpret_cast<float2*>(&C[(size_t)row1 * N + col]) = make_float2(x2, x3);
            }
        }
    }

    // ---- fused attdot epilogue (only when requested; bias/act are off for these GEMMs) ----
    if (aldot != nullptr) {
        int head = blockIdx.x;                       // BN=128 per head
        const float* aLh = attL + head * 128;
        const float* aRh = attR + head * 128;
        // stage this thread's 8 att values per side
        float aLv[4][2], aRv[4][2];
        #pragma unroll
        for (int ni = 0; ni < 4; ni++) {
            int cc = warpN * 32 + ni * 8 + c * 2;
            aLv[ni][0] = aLh[cc];     aLv[ni][1] = aLh[cc + 1];
            aRv[ni][0] = aRh[cc];     aRv[ni][1] = aRh[cc + 1];
        }
        #pragma unroll
        for (int mi = 0; mi < 4; mi++) {
            float al0 = 0.f, ar0 = 0.f, al1 = 0.f, ar1 = 0.f;
            #pragma unroll
            for (int ni = 0; ni < 4; ni++) {
                al0 += acc[mi][ni][0] * aLv[ni][0] + acc[mi][ni][1] * aLv[ni][1];
                ar0 += acc[mi][ni][0] * aRv[ni][0] + acc[mi][ni][1] * aRv[ni][1];
                al1 += acc[mi][ni][2] * aLv[ni][0] + acc[mi][ni][3] * aLv[ni][1];
                ar1 += acc[mi][ni][2] * aRv[ni][0] + acc[mi][ni][3] * aRv[ni][1];
            }
            // quad reduce over c (lanes g*4 .. g*4+3)
            #pragma unroll
            for (int o = 1; o < 4; o <<= 1) {
                al0 += __shfl_xor_sync(0xffffffffu, al0, o);
                ar0 += __shfl_xor_sync(0xffffffffu, ar0, o);
                al1 += __shfl_xor_sync(0xffffffffu, al1, o);
                ar1 += __shfl_xor_sync(0xffffffffu, ar1, o);
            }
            if (c == 0) {
                int lr0 = warpM * 64 + mi * 16 + g;
                redAL[lr0][warpN] = al0;  redAR[lr0][warpN] = ar0;
                redAL[lr0 + 8][warpN] = al1;  redAR[lr0 + 8][warpN] = ar1;
            }
        }
        __syncthreads();
        if (tid < BM) {
            int grow = bm + tid;
            if (grow < M) {
                float al = redAL[tid][0] + redAL[tid][1] + redAL[tid][2] + redAL[tid][3];
                float ar = redAR[tid][0] + redAR[tid][1] + redAR[tid][2] + redAR[tid][3];
                aldot[(size_t)grow * H + head] = al;
                ardot[(size_t)grow * H + head] = ar;
            }
        }
    }
}

// ---------------- SuperGAT aggregation: one warp per (node, head), 4-edge unroll ----------------
template<int H>
__global__ void agg_kernel(const float* __restrict__ feat,
                           const float* __restrict__ aldot, const float* __restrict__ ardot,
                           const float* __restrict__ bias,
                           const int* __restrict__ rowptr, const int* __restrict__ esrc,
                           float* __restrict__ out, float out_slope) {
    const int C = NHID;
    int warp = (blockIdx.x * blockDim.x + threadIdx.x) >> 5;
    int lane = threadIdx.x & 31;
    if (warp >= N_NODES * H) return;
    int nid = warp / H;
    int h   = warp % H;

    float4 xi = reinterpret_cast<const float4*>(feat + ((size_t)nid * H + h) * C)[lane];
    float ar = ardot[warp];

    float m = -INFINITY, s = 0.f;
    float4 acc = make_float4(0.f, 0.f, 0.f, 0.f);

    int e0 = rowptr[nid], e1 = rowptr[nid + 1];
    int e = e0;
    for (; e + 3 < e1; e += 4) {
        int s0 = esrc[e], s1 = esrc[e + 1], s2 = esrc[e + 2], s3 = esrc[e + 3];
        float4 xj0 = reinterpret_cast<const float4*>(feat + ((size_t)s0 * H + h) * C)[lane];
        float4 xj1 = reinterpret_cast<const float4*>(feat + ((size_t)s1 * H + h) * C)[lane];
        float4 xj2 = reinterpret_cast<const float4*>(feat + ((size_t)s2 * H + h) * C)[lane];
        float4 xj3 = reinterpret_cast<const float4*>(feat + ((size_t)s3 * H + h) * C)[lane];
        float lg0 = dot4(xi, xj0), lg1 = dot4(xi, xj1);
        float lg2 = dot4(xi, xj2), lg3 = dot4(xi, xj3);
        #pragma unroll
        for (int o = 16; o; o >>= 1) {
            lg0 += __shfl_xor_sync(0xffffffffu, lg0, o);
            lg1 += __shfl_xor_sync(0xffffffffu, lg1, o);
            lg2 += __shfl_xor_sync(0xffffffffu, lg2, o);
            lg3 += __shfl_xor_sync(0xffffffffu, lg3, o);
        }
        float a0 = (aldot[s0 * H + h] + ar) * (1.f / (1.f + __expf(-lg0)));
        float a1 = (aldot[s1 * H + h] + ar) * (1.f / (1.f + __expf(-lg1)));
        float a2 = (aldot[s2 * H + h] + ar) * (1.f / (1.f + __expf(-lg2)));
        float a3 = (aldot[s3 * H + h] + ar) * (1.f / (1.f + __expf(-lg3)));
        a0 = a0 > 0.f ? a0 : 0.2f * a0;
        a1 = a1 > 0.f ? a1 : 0.2f * a1;
        a2 = a2 > 0.f ? a2 : 0.2f * a2;
        a3 = a3 > 0.f ? a3 : 0.2f * a3;
        float mx = fmaxf(fmaxf(a0, a1), fmaxf(a2, a3));
        float mn = fmaxf(m, mx);
        float sc = __expf(m - mn);
        float w0 = __expf(a0 - mn), w1 = __expf(a1 - mn);
        float w2 = __expf(a2 - mn), w3 = __expf(a3 - mn);
        s = s * sc + w0 + w1 + w2 + w3;
        acc.x = acc.x * sc + w0 * xj0.x + w1 * xj1.x + w2 * xj2.x + w3 * xj3.x;
        acc.y = acc.y * sc + w0 * xj0.y + w1 * xj1.y + w2 * xj2.y + w3 * xj3.y;
        acc.z = acc.z * sc + w0 * xj0.z + w1 * xj1.z + w2 * xj2.z + w3 * xj3.z;
        acc.w = acc.w * sc + w0 * xj0.w + w1 * xj1.w + w2 * xj2.w + w3 * xj3.w;
        m = mn;
    }
    for (; e < e1; e++) {
        int sn = esrc[e];
        float4 xj = reinterpret_cast<const float4*>(feat + ((size_t)sn * H + h) * C)[lane];
        float lg = dot4(xi, xj);
        #pragma unroll
        for (int o = 16; o; o >>= 1) lg += __shfl_xor_sync(0xffffffffu, lg, o);
        float al = aldot[sn * H + h];
        float a = (al + ar) * (1.f / (1.f + __expf(-lg)));
        a = a > 0.f ? a : 0.2f * a;
        float mn = fmaxf(m, a);
        float sc = __expf(m - mn);
        float w = __expf(a - mn);
        s = s * sc + w;
        acc.x = acc.x * sc + w * xj.x;
        acc.y = acc.y * sc + w * xj.y;
        acc.z = acc.z * sc + w * xj.z;
        acc.w = acc.w * sc + w * xj.w;
        m = mn;
    }
    float inv = 1.f / (s + 1e-16f);
    float4 b4 = reinterpret_cast<const float4*>(bias + h * C)[lane];
    float4 r;
    r.x = acc.x * inv + b4.x; r.x = r.x > 0.f ? r.x : out_slope * r.x;
    r.y = acc.y * inv + b4.y; r.y = r.y > 0.f ? r.y : out_slope * r.y;
    r.z = acc.z * inv + b4.z; r.z = r.z > 0.f ? r.z : out_slope * r.z;
    r.w = acc.w * inv + b4.w; r.w = r.w > 0.f ? r.w : out_slope * r.w;
    reinterpret_cast<float4*>(out + ((size_t)nid * H + h) * C)[lane] = r;
}

// ---------------- graph pooling: one block per graph, no atomics ----------------
__global__ __launch_bounds__(NHID)
void pool_graph_kernel(const float* __restrict__ x, const int* __restrict__ batch,
                       float* __restrict__ pool) {
    int gph = blockIdx.x;
    int tid = threadIdx.x;
    __shared__ int s_lo, s_hi;
    if (tid == 0) {
        int lo = 0, hi = N_NODES;
        while (lo < hi) { int mid = (lo + hi) >> 1; if (batch[mid] < gph) lo = mid + 1; else hi = mid; }
        s_lo = lo;
        lo = 0; hi = N_NODES;
        while (lo < hi) { int mid = (lo + hi) >> 1; if (batch[mid] < gph + 1) lo = mid + 1; else hi = mid; }
        s_hi = lo;
    }
    __syncthreads();
    int lo = s_lo, hi = s_hi;
    float m = -FLT_MAX;
    int n = lo;
    for (; n + 3 < hi; n += 4) {
        float v0 = x[(size_t)(n + 0) * NHID + tid];
        float v1 = x[(size_t)(n + 1) * NHID + tid];
        float v2 = x[(size_t)(n + 2) * NHID + tid];
        float v3 = x[(size_t)(n + 3) * NHID + tid];
        m = fmaxf(m, fmaxf(fmaxf(v0, v1), fmaxf(v2, v3)));
    }
    for (; n < hi; n++) m = fmaxf(m, x[(size_t)n * NHID + tid]);
    pool[gph * NHID + tid] = m;
}

// ---------------- launch ----------------
static inline float* symf(const void* sym) {
    void* p = nullptr; cudaGetSymbolAddress(&p, sym); return (float*)p;
}
static inline int* symi(const void* sym) {
    void* p = nullptr; cudaGetSymbolAddress(&p, sym); return (int*)p;
}

extern "C" void kernel_launch(void* const* d_in, const int* in_sizes, int n_in,
                              void* d_out, int out_size) {
    const float* x      = (const float*)d_in[0];
    const int*   eidx   = (const int*)  d_in[1];
    const int*   batch  = (const int*)  d_in[2];
    const float* fc1_w  = (const float*)d_in[3];
    const float* fc1_b  = (const float*)d_in[4];
    const float* w1     = (const float*)d_in[5];
    const float* att_l1 = (const float*)d_in[6];
    const float* att_r1 = (const float*)d_in[7];
    const float* b1     = (const float*)d_in[8];
    const float* w2     = (const float*)d_in[9];
    const float* att_l2 = (const float*)d_in[10];
    const float* att_r2 = (const float*)d_in[11];
    const float* b2     = (const float*)d_in[12];
    const float* fc2_w  = (const float*)d_in[13];
    const float* fc2_b  = (const float*)d_in[14];
    float* out = (float*)d_out;

    const int* e_src = eidx;
    const int* e_dst = eidx + N_EDGES;

    float* h0 = symf(g_h0); float* f1 = symf(g_f1); float* o1 = symf(g_o1);
    float* f2 = symf(g_f2); float* o2 = symf(g_o2); float* pool = symf(g_pool);
    float* aldot = symf(g_aldot); float* ardot = symf(g_ardot);
    int* deg = symi(g_deg); int* rowptr = symi(g_rowptr);
    int* cursor = symi(g_cursor); int* esrc = symi(g_esrc);

    hist_kernel<<<(N_EDGES + 255) / 256, 256>>>(e_dst, deg, N_EDGES);                  // 0

    // GEMM1: h0 = leaky(x @ fc1_w + fc1_b)  BM=64
    {
        dim3 grid(NHID / 128, (N_NODES + 63) / 64);
        gemm_tf32_kernel<64, 1><<<grid, 128>>>(x, fc1_w, fc1_b, h0, N_NODES, NHID, N_IN,
                                               0.01f, 1, nullptr, nullptr, nullptr, nullptr); // 1
    }
    scan_kernel<<<1, 1024>>>(deg, rowptr, cursor);                                     // 2
    // GEMM2: f1 = h0 @ w1 + fused attdot (head = blockIdx.x)  (profiled slot 3, BM=128)
    {
        dim3 grid(HEADS * NHID / 128, (N_NODES + 127) / 128);
        gemm_tf32_kernel<128, HEADS><<<grid, 256>>>(h0, w1, nullptr, f1, N_NODES, HEADS * NHID, NHID,
                                                    0.f, 0, att_l1, att_r1, aldot, ardot); // 3
    }
    scatter_kernel<<<(N_EDGES + 255) / 256, 256>>>(e_src, e_dst, cursor, esrc, deg, N_EDGES); // 4

    // Aggregation layer 1
    {
        int warps = N_NODES * HEADS;
        agg_kernel<HEADS><<<(warps * 32 + 255) / 256, 256>>>(f1, aldot, ardot, b1,
                                                             rowptr, esrc, o1, 0.01f); // 5
    }
    // GEMM3: f2 = o1 @ w2 + fused attdot (H=1)  BM=64
    {
        dim3 grid(NHID / 128, (N_NODES + 63) / 64);
        gemm_tf32_kernel<64, 1><<<grid, 128>>>(o1, w2, nullptr, f2, N_NODES, NHID, HEADS * NHID,
                                               0.f, 0, att_l2, att_r2, aldot, ardot);  // 6
    }
    // Aggregation layer 2
    {
        int warps = N_NODES;
        agg_kernel<1><<<(warps * 32 + 255) / 256, 256>>>(f2, aldot, ardot, b2,
                                                         rowptr, esrc, o2, 0.01f);     // 7
    }
    // Pooling
    pool_graph_kernel<<<NUM_GRAPHS, NHID>>>(o2, batch, pool);                          // 8

    // GEMM4: out = pool @ fc2_w + fc2_b  BM=64
    {
        dim3 grid(NOUT / 128, (NUM_GRAPHS + 63) / 64);
        gemm_tf32_kernel<64, 1><<<grid, 128>>>(pool, fc2_w, fc2_b, out, NUM_GRAPHS, NOUT, NHID,
                                               0.f, 0, nullptr, nullptr, nullptr, nullptr); // 9
    }
}

// round 15
// speedup vs baseline: 1.1010x; 1.0020x over previous
#include <cuda_runtime.h>
#include <cuda_bf16.h>
#include <cuda_fp16.h>
#include <cfloat>
#include <math.h>

// ---------------- problem constants ----------------
#define N_NODES   20000
#define N_EDGES   160000
#define N_IN      300
#define NHID      128
#define HEADS     4
#define NOUT      768
#define NUM_GRAPHS 128

typedef unsigned long long ull;

// ---------------- scratch ----------------
__device__ float  g_h0[N_NODES * NHID];
__device__ __half g_f1h[N_NODES * HEADS * NHID];   // fp16 features for agg1
__device__ float  g_o1[N_NODES * HEADS * NHID];
__device__ __half g_f2h[N_NODES * NHID];           // fp16 features for agg2
__device__ float  g_o2[N_NODES * NHID];
__device__ float  g_aldot[N_NODES * HEADS];
__device__ float  g_ardot[N_NODES * HEADS];
__device__ int    g_deg[N_NODES];                  // zero-init; re-zeroed by scatter each call
__device__ int    g_rowptr[N_NODES + 1];
__device__ int    g_cursor[N_NODES];
__device__ int    g_esrc[N_EDGES];
__device__ float  g_pool[NUM_GRAPHS * NHID];

// ---------------- tf32 helpers ----------------
__device__ __forceinline__ unsigned f2tf32(float f) {
    unsigned u;
    asm("cvt.rna.tf32.f32 %0, %1;" : "=r"(u) : "f"(f));
    return u;
}
__device__ __forceinline__ void mma_tf32(float& d0, float& d1, float& d2, float& d3,
                                         unsigned a0, unsigned a1, unsigned a2, unsigned a3,
                                         unsigned b0, unsigned b1) {
    asm("mma.sync.aligned.m16n8k8.row.col.f32.tf32.tf32.f32 "
        "{%0,%1,%2,%3}, {%4,%5,%6,%7}, {%8,%9}, {%0,%1,%2,%3};"
        : "+f"(d0), "+f"(d1), "+f"(d2), "+f"(d3)
        : "r"(a0), "r"(a1), "r"(a2), "r"(a3), "r"(b0), "r"(b1));
}

__device__ __forceinline__ float dot4(float4 a, float4 b) {
    return a.x * b.x + a.y * b.y + a.z * b.z + a.w * b.w;
}
// load 4 halves (8B) as float4
__device__ __forceinline__ float4 ldh4(const __half* base, int idx4) {
    uint2 r = reinterpret_cast<const uint2*>(base)[idx4];
    __half2 h0 = *reinterpret_cast<__half2*>(&r.x);
    __half2 h1 = *reinterpret_cast<__half2*>(&r.y);
    float2 f0 = __half22float2(h0);
    float2 f1 = __half22float2(h1);
    return make_float4(f0.x, f0.y, f1.x, f1.y);
}

// ---------------- CSR build ----------------
__global__ void hist_kernel(const int* __restrict__ dst, int* __restrict__ deg, int E) {
    int i = blockIdx.x * blockDim.x + threadIdx.x;
    if (i < E) atomicAdd(&deg[dst[i]], 1);
}

__global__ void scan_kernel(const int* __restrict__ deg, int* __restrict__ rowptr,
                            int* __restrict__ cursor) {
    __shared__ int sh[1024];
    const int PER = 20;
    int tid = threadIdx.x;
    int base = tid * PER;
    int loc[PER];
    int s = 0;
    #pragma unroll
    for (int i = 0; i < PER; i++) {
        int idx = base + i;
        int v = (idx < N_NODES) ? deg[idx] : 0;
        loc[i] = s;
        s += v;
    }
    sh[tid] = s;
    __syncthreads();
    #pragma unroll
    for (int off = 1; off < 1024; off <<= 1) {
        int t = (tid >= off) ? sh[tid - off] : 0;
        __syncthreads();
        sh[tid] += t;
        __syncthreads();
    }
    int prev = (tid > 0) ? sh[tid - 1] : 0;
    #pragma unroll
    for (int i = 0; i < PER; i++) {
        int idx = base + i;
        if (idx < N_NODES) {
            int v = prev + loc[i];
            rowptr[idx] = v;
            cursor[idx] = v;
        }
    }
    if (tid == 1023) rowptr[N_NODES] = sh[1023];
}

__global__ void scatter_kernel(const int* __restrict__ src, const int* __restrict__ dst,
                               int* __restrict__ cursor, int* __restrict__ esrc,
                               int* __restrict__ deg, int E) {
    int i = blockIdx.x * blockDim.x + threadIdx.x;
    if (i < N_NODES) deg[i] = 0;
    if (i < E) {
        int d = dst[i];
        int p = atomicAdd(&cursor[d], 1);
        esrc[p] = src[i];
    }
}

// ---------------- tf32 tensor-core GEMM, double-buffered, fused attdot, optional half out ----------------
template<int BM, int H>
__global__ __launch_bounds__(2 * BM)
void gemm_tf32_kernel(const float* __restrict__ A, const float* __restrict__ B,
                      const float* __restrict__ bias, float* __restrict__ C,
                      __half* __restrict__ Ch,
                      int M, int N, int K, float slope, int act,
                      const float* __restrict__ attL, const float* __restrict__ attR,
                      float* __restrict__ aldot, float* __restrict__ ardot) {
    const int BK = 16;
    const int ASTR = BM + 8;
    const int THREADS = 2 * BM;
    const int BROWS = THREADS / 16;
    const int BPASS = 16 / BROWS;
    __shared__ __align__(16) unsigned As[2][BK * ASTR];
    __shared__ __align__(16) unsigned Bs[2][32 * 33 * 2];
    __shared__ float redAL[BM][4];
    __shared__ float redAR[BM][4];

    int tid = threadIdx.x;
    int lane = tid & 31;
    int wid = tid >> 5;
    int warpM = wid >> 2;
    int warpN = wid & 3;
    int bm = blockIdx.y * BM, bn = blockIdx.x * 128;
    int g = lane >> 2, c = lane & 3;

    float acc[4][4][4];
    #pragma unroll
    for (int mi = 0; mi < 4; mi++)
        #pragma unroll
        for (int ni = 0; ni < 4; ni++)
            #pragma unroll
            for (int r = 0; r < 4; r++) acc[mi][ni][r] = 0.f;

    int la_m = tid >> 1;
    int la_k = (tid & 1) * 8;
    int gmA = bm + la_m;
    int pa_m = (la_m & ~15) | ((la_m & 7) << 1) | ((la_m >> 3) & 1);
    int lbn = (tid & 15) * 8;
    int b_nb = tid & 15;

    float4 pa0, pa1;
    float pbv[BPASS][8];

    int nT = (K + BK - 1) / BK;

    auto load_tile = [&](int k0) {
        pa0 = make_float4(0.f, 0.f, 0.f, 0.f);
        pa1 = make_float4(0.f, 0.f, 0.f, 0.f);
        int gk0 = k0 + la_k;
        if (gmA < M && gk0 < K)
            pa0 = *reinterpret_cast<const float4*>(&A[(size_t)gmA * K + gk0]);
        if (gmA < M && gk0 + 4 < K)
            pa1 = *reinterpret_cast<const float4*>(&A[(size_t)gmA * K + gk0 + 4]);
        #pragma unroll
        for (int pass = 0; pass < BPASS; pass++) {
            int lbk = (tid >> 4) + pass * BROWS;
            int gk = k0 + lbk;
            float4 v0 = make_float4(0.f, 0.f, 0.f, 0.f);
            float4 v1 = make_float4(0.f, 0.f, 0.f, 0.f);
            if (gk < K) {
                v0 = *reinterpret_cast<const float4*>(&B[(size_t)gk * N + bn + lbn]);
                v1 = *reinterpret_cast<const float4*>(&B[(size_t)gk * N + bn + lbn + 4]);
            }
            pbv[pass][0] = v0.x; pbv[pass][1] = v0.y; pbv[pass][2] = v0.z; pbv[pass][3] = v0.w;
            pbv[pass][4] = v1.x; pbv[pass][5] = v1.y; pbv[pass][6] = v1.z; pbv[pass][7] = v1.w;
        }
    };
    auto store_tile = [&](int buf) {
        As[buf][(la_k + 0) * ASTR + pa_m] = f2tf32(pa0.x);
        As[buf][(la_k + 1) * ASTR + pa_m] = f2tf32(pa0.y);
        As[buf][(la_k + 2) * ASTR + pa_m] = f2tf32(pa0.z);
        As[buf][(la_k + 3) * ASTR + pa_m] = f2tf32(pa0.w);
        As[buf][(la_k + 4) * ASTR + pa_m] = f2tf32(pa1.x);
        As[buf][(la_k + 5) * ASTR + pa_m] = f2tf32(pa1.y);
        As[buf][(la_k + 6) * ASTR + pa_m] = f2tf32(pa1.z);
        As[buf][(la_k + 7) * ASTR + pa_m] = f2tf32(pa1.w);
        #pragma unroll
        for (int pass = 0; pass < BPASS; pass++) {
            int lbk = (tid >> 4) + pass * BROWS;
            int b_kb = lbk >> 3;
            int b_c = lbk & 3;
            int b_half = (lbk & 7) >> 2;
            int grp = b_kb * 16 + b_nb;
            #pragma unroll
            for (int j = 0; j < 8; j++) {
                int u = grp * 33 + j * 4 + b_c;
                Bs[buf][2 * u + b_half] = f2tf32(pbv[pass][j]);
            }
        }
    };

    load_tile(0);
    store_tile(0);
    __syncthreads();

    for (int t = 0; t < nT; t++) {
        int buf = t & 1;
        bool more = (t + 1) < nT;
        if (more) load_tile((t + 1) * BK);

        #pragma unroll
        for (int kb = 0; kb < 2; kb++) {
            unsigned af[4][4];
            int r0 = (kb * 8 + c) * ASTR;
            int r1 = (kb * 8 + c + 4) * ASTR;
            #pragma unroll
            for (int mi = 0; mi < 4; mi++) {
                int m0 = warpM * 64 + mi * 16;
                uint2 p0 = *reinterpret_cast<const uint2*>(&As[buf][r0 + m0 + 2 * g]);
                uint2 p1 = *reinterpret_cast<const uint2*>(&As[buf][r1 + m0 + 2 * g]);
                af[mi][0] = p0.x;
                af[mi][1] = p0.y;
                af[mi][2] = p1.x;
                af[mi][3] = p1.y;
            }
            unsigned bf[4][2];
            #pragma unroll
            for (int ni = 0; ni < 4; ni++) {
                int grp = kb * 16 + warpN * 4 + ni;
                uint2 tt = *reinterpret_cast<const uint2*>(&Bs[buf][2 * (grp * 33 + lane)]);
                bf[ni][0] = tt.x;
                bf[ni][1] = tt.y;
            }
            #pragma unroll
            for (int mi = 0; mi < 4; mi++)
                #pragma unroll
                for (int ni = 0; ni < 4; ni++)
                    mma_tf32(acc[mi][ni][0], acc[mi][ni][1], acc[mi][ni][2], acc[mi][ni][3],
                             af[mi][0], af[mi][1], af[mi][2], af[mi][3],
                             bf[ni][0], bf[ni][1]);
        }

        if (more) store_tile(1 - buf);
        __syncthreads();
    }

    // ---- main epilogue: bias/act + store (float or half) ----
    #pragma unroll
    for (int mi = 0; mi < 4; mi++) {
        int row0 = bm + warpM * 64 + mi * 16 + g;
        #pragma unroll
        for (int ni = 0; ni < 4; ni++) {
            int col = bn + warpN * 32 + ni * 8 + c * 2;
            float bv0 = bias ? bias[col] : 0.f;
            float bv1 = bias ? bias[col + 1] : 0.f;
            if (row0 < M) {
                float x0 = acc[mi][ni][0] + bv0;
                float x1 = acc[mi][ni][1] + bv1;
                if (act) {
                    x0 = x0 > 0.f ? x0 : slope * x0;
                    x1 = x1 > 0.f ? x1 : slope * x1;
                }
                if (Ch) *reinterpret_cast<__half2*>(&Ch[(size_t)row0 * N + col]) = __floats2half2_rn(x0, x1);
                else    *reinterpret_cast<float2*>(&C[(size_t)row0 * N + col]) = make_float2(x0, x1);
            }
            int row1 = row0 + 8;
            if (row1 < M) {
                float x2 = acc[mi][ni][2] + bv0;
                float x3 = acc[mi][ni][3] + bv1;
                if (act) {
                    x2 = x2 > 0.f ? x2 : slope * x2;
                    x3 = x3 > 0.f ? x3 : slope * x3;
                }
                if (Ch) *reinterpret_cast<__half2*>(&Ch[(size_t)row1 * N + col]) = __floats2half2_rn(x2, x3);
                else    *reinterpret_cast<float2*>(&C[(size_t)row1 * N + col]) = make_float2(x2, x3);
            }
        }
    }

    // ---- fused attdot epilogue ----
    if (aldot != nullptr) {
        int head = blockIdx.x;
        const float* aLh = attL + head * 128;
        const float* aRh = attR + head * 128;
        float aLv[4][2], aRv[4][2];
        #pragma unroll
        for (int ni = 0; ni < 4; ni++) {
            int cc = warpN * 32 + ni * 8 + c * 2;
            aLv[ni][0] = aLh[cc];     aLv[ni][1] = aLh[cc + 1];
            aRv[ni][0] = aRh[cc];     aRv[ni][1] = aRh[cc + 1];
        }
        #pragma unroll
        for (int mi = 0; mi < 4; mi++) {
            float al0 = 0.f, ar0 = 0.f, al1 = 0.f, ar1 = 0.f;
            #pragma unroll
            for (int ni = 0; ni < 4; ni++) {
                al0 += acc[mi][ni][0] * aLv[ni][0] + acc[mi][ni][1] * aLv[ni][1];
                ar0 += acc[mi][ni][0] * aRv[ni][0] + acc[mi][ni][1] * aRv[ni][1];
                al1 += acc[mi][ni][2] * aLv[ni][0] + acc[mi][ni][3] * aLv[ni][1];
                ar1 += acc[mi][ni][2] * aRv[ni][0] + acc[mi][ni][3] * aRv[ni][1];
            }
            #pragma unroll
            for (int o = 1; o < 4; o <<= 1) {
                al0 += __shfl_xor_sync(0xffffffffu, al0, o);
                ar0 += __shfl_xor_sync(0xffffffffu, ar0, o);
                al1 += __shfl_xor_sync(0xffffffffu, al1, o);
                ar1 += __shfl_xor_sync(0xffffffffu, ar1, o);
            }
            if (c == 0) {
                int lr0 = warpM * 64 + mi * 16 + g;
                redAL[lr0][warpN] = al0;  redAR[lr0][warpN] = ar0;
                redAL[lr0 + 8][warpN] = al1;  redAR[lr0 + 8][warpN] = ar1;
            }
        }
        __syncthreads();
        if (tid < BM) {
            int grow = bm + tid;
            if (grow < M) {
                float al = redAL[tid][0] + redAL[tid][1] + redAL[tid][2] + redAL[tid][3];
                float ar = redAR[tid][0] + redAR[tid][1] + redAR[tid][2] + redAR[tid][3];
                aldot[(size_t)grow * H + head] = al;
                ardot[(size_t)grow * H + head] = ar;
            }
        }
    }
}

// ---------------- SuperGAT aggregation: half features, one warp per (node, head) ----------------
template<int H>
__global__ void agg_kernel(const __half* __restrict__ feat,
                           const float* __restrict__ aldot, const float* __restrict__ ardot,
                           const float* __restrict__ bias,
                           const int* __restrict__ rowptr, const int* __restrict__ esrc,
                           float* __restrict__ out, float out_slope) {
    const int C = NHID;
    int warp = (blockIdx.x * blockDim.x + threadIdx.x) >> 5;
    int lane = threadIdx.x & 31;
    if (warp >= N_NODES * H) return;
    int nid = warp / H;
    int h   = warp % H;

    float4 xi = ldh4(feat + ((size_t)nid * H + h) * C, lane);
    float ar = ardot[warp];

    float m = -INFINITY, s = 0.f;
    float4 acc = make_float4(0.f, 0.f, 0.f, 0.f);

    int e0 = rowptr[nid], e1 = rowptr[nid + 1];
    int e = e0;
    for (; e + 3 < e1; e += 4) {
        int s0 = esrc[e], s1 = esrc[e + 1], s2 = esrc[e + 2], s3 = esrc[e + 3];
        float4 xj0 = ldh4(feat + ((size_t)s0 * H + h) * C, lane);
        float4 xj1 = ldh4(feat + ((size_t)s1 * H + h) * C, lane);
        float4 xj2 = ldh4(feat + ((size_t)s2 * H + h) * C, lane);
        float4 xj3 = ldh4(feat + ((size_t)s3 * H + h) * C, lane);
        float lg0 = dot4(xi, xj0), lg1 = dot4(xi, xj1);
        float lg2 = dot4(xi, xj2), lg3 = dot4(xi, xj3);
        #pragma unroll
        for (int o = 16; o; o >>= 1) {
            lg0 += __shfl_xor_sync(0xffffffffu, lg0, o);
            lg1 += __shfl_xor_sync(0xffffffffu, lg1, o);
            lg2 += __shfl_xor_sync(0xffffffffu, lg2, o);
            lg3 += __shfl_xor_sync(0xffffffffu, lg3, o);
        }
        float a0 = (aldot[s0 * H + h] + ar) * (1.f / (1.f + __expf(-lg0)));
        float a1 = (aldot[s1 * H + h] + ar) * (1.f / (1.f + __expf(-lg1)));
        float a2 = (aldot[s2 * H + h] + ar) * (1.f / (1.f + __expf(-lg2)));
        float a3 = (aldot[s3 * H + h] + ar) * (1.f / (1.f + __expf(-lg3)));
        a0 = a0 > 0.f ? a0 : 0.2f * a0;
        a1 = a1 > 0.f ? a1 : 0.2f * a1;
        a2 = a2 > 0.f ? a2 : 0.2f * a2;
        a3 = a3 > 0.f ? a3 : 0.2f * a3;
        float mx = fmaxf(fmaxf(a0, a1), fmaxf(a2, a3));
        float mn = fmaxf(m, mx);
        float sc = __expf(m - mn);
        float w0 = __expf(a0 - mn), w1 = __expf(a1 - mn);
        float w2 = __expf(a2 - mn), w3 = __expf(a3 - mn);
        s = s * sc + w0 + w1 + w2 + w3;
        acc.x = acc.x * sc + w0 * xj0.x + w1 * xj1.x + w2 * xj2.x + w3 * xj3.x;
        acc.y = acc.y * sc + w0 * xj0.y + w1 * xj1.y + w2 * xj2.y + w3 * xj3.y;
        acc.z = acc.z * sc + w0 * xj0.z + w1 * xj1.z + w2 * xj2.z + w3 * xj3.z;
        acc.w = acc.w * sc + w0 * xj0.w + w1 * xj1.w + w2 * xj2.w + w3 * xj3.w;
        m = mn;
    }
    for (; e < e1; e++) {
        int sn = esrc[e];
        float4 xj = ldh4(feat + ((size_t)sn * H + h) * C, lane);
        float lg = dot4(xi, xj);
        #pragma unroll
        for (int o = 16; o; o >>= 1) lg += __shfl_xor_sync(0xffffffffu, lg, o);
        float al = aldot[sn * H + h];
        float a = (al + ar) * (1.f / (1.f + __expf(-lg)));
        a = a > 0.f ? a : 0.2f * a;
        float mn = fmaxf(m, a);
        float sc = __expf(m - mn);
        float w = __expf(a - mn);
        s = s * sc + w;
        acc.x = acc.x * sc + w * xj.x;
        acc.y = acc.y * sc + w * xj.y;
        acc.z = acc.z * sc + w * xj.z;
        acc.w = acc.w * sc + w * xj.w;
        m = mn;
    }
    float inv = 1.f / (s + 1e-16f);
    float4 b4 = reinterpret_cast<const float4*>(bias + h * C)[lane];
    float4 r;
    r.x = acc.x * inv + b4.x; r.x = r.x > 0.f ? r.x : out_slope * r.x;
    r.y = acc.y * inv + b4.y; r.y = r.y > 0.f ? r.y : out_slope * r.y;
    r.z = acc.z * inv + b4.z; r.z = r.z > 0.f ? r.z : out_slope * r.z;
    r.w = acc.w * inv + b4.w; r.w = r.w > 0.f ? r.w : out_slope * r.w;
    reinterpret_cast<float4*>(out + ((size_t)nid * H + h) * C)[lane] = r;
}

// ---------------- graph pooling: one block per graph, no atomics ----------------
__global__ __launch_bounds__(NHID)
void pool_graph_kernel(const float* __restrict__ x, const int* __restrict__ batch,
                       float* __restrict__ pool) {
    int gph = blockIdx.x;
    int tid = threadIdx.x;
    __shared__ int s_lo, s_hi;
    if (tid == 0) {
        int lo = 0, hi = N_NODES;
        while (lo < hi) { int mid = (lo + hi) >> 1; if (batch[mid] < gph) lo = mid + 1; else hi = mid; }
        s_lo = lo;
        lo = 0; hi = N_NODES;
        while (lo < hi) { int mid = (lo + hi) >> 1; if (batch[mid] < gph + 1) lo = mid + 1; else hi = mid; }
        s_hi = lo;
    }
    __syncthreads();
    int lo = s_lo, hi = s_hi;
    float m = -FLT_MAX;
    int n = lo;
    for (; n + 3 < hi; n += 4) {
        float v0 = x[(size_t)(n + 0) * NHID + tid];
        float v1 = x[(size_t)(n + 1) * NHID + tid];
        float v2 = x[(size_t)(n + 2) * NHID + tid];
        float v3 = x[(size_t)(n + 3) * NHID + tid];
        m = fmaxf(m, fmaxf(fmaxf(v0, v1), fmaxf(v2, v3)));
    }
    for (; n < hi; n++) m = fmaxf(m, x[(size_t)n * NHID + tid]);
    pool[gph * NHID + tid] = m;
}

// ---------------- launch ----------------
static inline float* symf(const void* sym) {
    void* p = nullptr; cudaGetSymbolAddress(&p, sym); return (float*)p;
}
static inline int* symi(const void* sym) {
    void* p = nullptr; cudaGetSymbolAddress(&p, sym); return (int*)p;
}
static inline __half* symh(const void* sym) {
    void* p = nullptr; cudaGetSymbolAddress(&p, sym); return (__half*)p;
}

extern "C" void kernel_launch(void* const* d_in, const int* in_sizes, int n_in,
                              void* d_out, int out_size) {
    const float* x      = (const float*)d_in[0];
    const int*   eidx   = (const int*)  d_in[1];
    const int*   batch  = (const int*)  d_in[2];
    const float* fc1_w  = (const float*)d_in[3];
    const float* fc1_b  = (const float*)d_in[4];
    const float* w1     = (const float*)d_in[5];
    const float* att_l1 = (const float*)d_in[6];
    const float* att_r1 = (const float*)d_in[7];
    const float* b1     = (const float*)d_in[8];
    const float* w2     = (const float*)d_in[9];
    const float* att_l2 = (const float*)d_in[10];
    const float* att_r2 = (const float*)d_in[11];
    const float* b2     = (const float*)d_in[12];
    const float* fc2_w  = (const float*)d_in[13];
    const float* fc2_b  = (const float*)d_in[14];
    float* out = (float*)d_out;

    const int* e_src = eidx;
    const int* e_dst = eidx + N_EDGES;

    float* h0 = symf(g_h0); float* o1 = symf(g_o1); float* o2 = symf(g_o2);
    __half* f1h = symh(g_f1h); __half* f2h = symh(g_f2h);
    float* pool = symf(g_pool);
    float* aldot = symf(g_aldot); float* ardot = symf(g_ardot);
    int* deg = symi(g_deg); int* rowptr = symi(g_rowptr);
    int* cursor = symi(g_cursor); int* esrc = symi(g_esrc);

    hist_kernel<<<(N_EDGES + 255) / 256, 256>>>(e_dst, deg, N_EDGES);                  // 0

    // GEMM1: h0 = leaky(x @ fc1_w + fc1_b)  BM=64, float out
    {
        dim3 grid(NHID / 128, (N_NODES + 63) / 64);
        gemm_tf32_kernel<64, 1><<<grid, 128>>>(x, fc1_w, fc1_b, h0, nullptr,
                                               N_NODES, NHID, N_IN, 0.01f, 1,
                                               nullptr, nullptr, nullptr, nullptr);    // 1
    }
    scan_kernel<<<1, 1024>>>(deg, rowptr, cursor);                                     // 2
    // GEMM2: f1h = half(h0 @ w1) + fused attdot  (profiled slot 3, BM=128)
    {
        dim3 grid(HEADS * NHID / 128, (N_NODES + 127) / 128);
        gemm_tf32_kernel<128, HEADS><<<grid, 256>>>(h0, w1, nullptr, nullptr, f1h,
                                                    N_NODES, HEADS * NHID, NHID, 0.f, 0,
                                                    att_l1, att_r1, aldot, ardot);     // 3
    }
    scatter_kernel<<<(N_EDGES + 255) / 256, 256>>>(e_src, e_dst, cursor, esrc, deg, N_EDGES); // 4

    // Aggregation layer 1 (half features)
    {
        int warps = N_NODES * HEADS;
        agg_kernel<HEADS><<<(warps * 32 + 255) / 256, 256>>>(f1h, aldot, ardot, b1,
                                                             rowptr, esrc, o1, 0.01f); // 5
    }
    // GEMM3: f2h = half(o1 @ w2) + fused attdot (H=1)  BM=64
    {
        dim3 grid(NHID / 128, (N_NODES + 63) / 64);
        gemm_tf32_kernel<64, 1><<<grid, 128>>>(o1, w2, nullptr, nullptr, f2h,
                                               N_NODES, NHID, HEADS * NHID, 0.f, 0,
                                               att_l2, att_r2, aldot, ardot);          // 6
    }
    // Aggregation layer 2 (half features)
    {
        int warps = N_NODES;
        agg_kernel<1><<<(warps * 32 + 255) / 256, 256>>>(f2h, aldot, ardot, b2,
                                                         rowptr, esrc, o2, 0.01f);     // 7
    }
    // Pooling
    pool_graph_kernel<<<NUM_GRAPHS, NHID>>>(o2, batch, pool);                          // 8

    // GEMM4: out = pool @ fc2_w + fc2_b  BM=64, float out
    {
        dim3 grid(NOUT / 128, (NUM_GRAPHS + 63) / 64);
        gemm_tf32_kernel<64, 1><<<grid, 128>>>(pool, fc2_w, fc2_b, out, nullptr,
                                               NUM_GRAPHS, NOUT, NHID, 0.f, 0,
                                               nullptr, nullptr, nullptr, nullptr);    // 9
    }
}